// round 1
// baseline (speedup 1.0000x reference)
#include <cuda_runtime.h>
#include <math.h>

#define BB 16
#define CC 128
#define NN 16384
#define SQRTC 11.313708498984761f

// ---- scratch (static __device__ per allocation rules) ----
__device__ float g_q[BB*CC*NN];       // q logits, 128 MiB
__device__ float g_WT[3*CC*CC];       // qkv weights, transposed [g][k][o], g1*sqrtC folded
__device__ float g_WoT[CC*CC];        // out weights transposed [e][o]
__device__ float g_ctx[BB*4*32*32];   // context numerators
__device__ float g_den[BB*CC];        // context denominators

typedef unsigned long long ull;

__device__ __forceinline__ ull fma2(ull a, ull b, ull c) {
    ull d; asm("fma.rn.f32x2 %0, %1, %2, %3;" : "=l"(d) : "l"(a), "l"(b), "l"(c)); return d;
}
__device__ __forceinline__ ull mul2(ull a, ull b) {
    ull d; asm("mul.rn.f32x2 %0, %1, %2;" : "=l"(d) : "l"(a), "l"(b)); return d;
}
__device__ __forceinline__ ull pack2(float lo, float hi) {
    ull r; asm("mov.b64 %0, {%1, %2};" : "=l"(r) : "f"(lo), "f"(hi)); return r;
}

union U8 { ull u[4]; float f[8]; float4 v4[2]; };

// ---------------------------------------------------------------------------
// prep: transpose/scale weights, zero accumulators (re-run every launch)
// ---------------------------------------------------------------------------
__global__ void prep_kernel(const float* __restrict__ wqkv, const float* __restrict__ g1,
                            const float* __restrict__ wout) {
    int i = blockIdx.x * 256 + threadIdx.x;
    if (i < 3*CC*CC) {
        int g = i / (CC*CC); int r = i % (CC*CC); int kk = r >> 7; int o = r & 127;
        g_WT[i] = wqkv[((g<<7)+o)*CC + kk] * g1[kk] * SQRTC;
    }
    if (i < CC*CC) { int e = i >> 7, o = i & 127; g_WoT[i] = wout[(o<<7)+e]; }
    if (i < BB*4096) g_ctx[i] = 0.f;
    if (i < BB*CC)   g_den[i] = 0.f;
}

// ---------------------------------------------------------------------------
// K1: per 128-token tile: rmsnorm + QKV GEMM (f32x2), store q logits,
//     exp(k) (no-max softmax numerator), ctx += exp(k) v^T, den += exp(k)
// smem: Xs[128c][128t] @0 (64K) | Ws/Vs @65536 (66K) | Ek @133120 (66K) | inv @200704
// ---------------------------------------------------------------------------
#define K1_SMEM 201216

__global__ __launch_bounds__(256,1) void qkv_kernel(const float* __restrict__ x) {
    extern __shared__ char sm[];
    float* Xs  = (float*)(sm);
    float* Ws  = (float*)(sm + 65536);
    float* Ek  = (float*)(sm + 133120);
    float* Vs  = Ws;                       // reused after v-group k-loop
    float* inv = (float*)(sm + 200704);

    const int tid = threadIdx.x, tx = tid & 15, ox = tid >> 4;
    const int b = blockIdx.y; const int p0 = blockIdx.x << 7;

    float4* Xs4 = (float4*)Xs;
    for (int i = tid; i < 4096; i += 256) {
        int c = i >> 5, t4 = i & 31;
        Xs4[i] = *((const float4*)(x + (((size_t)((b<<7)+c))<<14) + p0) + t4);
    }
    __syncthreads();
    if (tid < 128) {
        float s = 0.f;
        #pragma unroll 16
        for (int c = 0; c < 128; c++) { float v = Xs[(c<<7)+tid]; s = fmaf(v, v, s); }
        inv[tid] = 1.0f / fmaxf(sqrtf(s), 1e-12f);
    }
    __syncthreads();

    const ull* XsU  = (const ull*)Xs;
    const ull* invU = (const ull*)inv;
    float4* Ws4 = (float4*)Ws;

    for (int g = 0; g < 3; g++) {
        __syncthreads();
        {
            const float4* wg = (const float4*)(g_WT + g*(CC*CC));
            for (int i = tid; i < 4096; i += 256) Ws4[i] = wg[i];
        }
        __syncthreads();

        ull acc[8][4];
        #pragma unroll
        for (int oi = 0; oi < 8; oi++) { acc[oi][0]=0; acc[oi][1]=0; acc[oi][2]=0; acc[oi][3]=0; }

        #pragma unroll 4
        for (int kk = 0; kk < 128; kk++) {
            float4 w0 = Ws4[(kk<<5)+(ox<<1)];
            float4 w1 = Ws4[(kk<<5)+(ox<<1)+1];
            ull xp[4];
            xp[0] = XsU[(kk<<6)+(tx<<2)];
            xp[1] = XsU[(kk<<6)+(tx<<2)+1];
            xp[2] = XsU[(kk<<6)+(tx<<2)+2];
            xp[3] = XsU[(kk<<6)+(tx<<2)+3];
            ull wp[8];
            wp[0]=pack2(w0.x,w0.x); wp[1]=pack2(w0.y,w0.y); wp[2]=pack2(w0.z,w0.z); wp[3]=pack2(w0.w,w0.w);
            wp[4]=pack2(w1.x,w1.x); wp[5]=pack2(w1.y,w1.y); wp[6]=pack2(w1.z,w1.z); wp[7]=pack2(w1.w,w1.w);
            #pragma unroll
            for (int oi = 0; oi < 8; oi++) {
                acc[oi][0] = fma2(wp[oi], xp[0], acc[oi][0]);
                acc[oi][1] = fma2(wp[oi], xp[1], acc[oi][1]);
                acc[oi][2] = fma2(wp[oi], xp[2], acc[oi][2]);
                acc[oi][3] = fma2(wp[oi], xp[3], acc[oi][3]);
            }
        }

        ull ip[4];
        ip[0]=invU[(tx<<2)]; ip[1]=invU[(tx<<2)+1]; ip[2]=invU[(tx<<2)+2]; ip[3]=invU[(tx<<2)+3];

        if (g == 0) {           // q: scale by inv, store logits to global
            #pragma unroll
            for (int oi = 0; oi < 8; oi++) {
                U8 r;
                r.u[0]=mul2(acc[oi][0],ip[0]); r.u[1]=mul2(acc[oi][1],ip[1]);
                r.u[2]=mul2(acc[oi][2],ip[2]); r.u[3]=mul2(acc[oi][3],ip[3]);
                int o = (ox<<3)+oi;
                float4* dst = (float4*)(g_q + (((size_t)((b<<7)+o))<<14) + p0 + (tx<<3));
                dst[0]=r.v4[0]; dst[1]=r.v4[1];
            }
        } else if (g == 1) {    // k: exp(k logits) -> Ek smem; den accumulation
            #pragma unroll
            for (int oi = 0; oi < 8; oi++) {
                U8 r, e;
                r.u[0]=mul2(acc[oi][0],ip[0]); r.u[1]=mul2(acc[oi][1],ip[1]);
                r.u[2]=mul2(acc[oi][2],ip[2]); r.u[3]=mul2(acc[oi][3],ip[3]);
                #pragma unroll
                for (int j = 0; j < 8; j++) e.f[j] = __expf(r.f[j]);
                int o = (ox<<3)+oi;
                float4* dst = (float4*)(Ek + o*132 + (tx<<3));
                dst[0]=e.v4[0]; dst[1]=e.v4[1];
            }
            __syncthreads();
            if (tid < 128) {
                float s = 0.f;
                const float4* row = (const float4*)(Ek + tid*132);
                #pragma unroll 8
                for (int t4 = 0; t4 < 32; t4++) { float4 v = row[t4]; s += v.x+v.y+v.z+v.w; }
                atomicAdd(&g_den[(b<<7)+tid], s);
            }
        } else {                // v: scale by inv -> Vs smem; ctx accumulation
            __syncthreads();    // all Ws reads (k-loop) done before overwrite as Vs
            #pragma unroll
            for (int oi = 0; oi < 8; oi++) {
                U8 r;
                r.u[0]=mul2(acc[oi][0],ip[0]); r.u[1]=mul2(acc[oi][1],ip[1]);
                r.u[2]=mul2(acc[oi][2],ip[2]); r.u[3]=mul2(acc[oi][3],ip[3]);
                int o = (ox<<3)+oi;
                float4* dst = (float4*)(Vs + o*132 + (tx<<3));
                dst[0]=r.v4[0]; dst[1]=r.v4[1];
            }
            __syncthreads();
            // ctx[h][d][e] += sum_t Ek[h*32+d][t] * Vs[h*32+e][t]
            const int h = tid >> 6, idx = tid & 63, d0 = idx & 7, e0 = idx >> 3;
            const float* ekb = Ek + (h<<5)*132;
            const float* vvb = Vs + (h<<5)*132;
            float cacc[4][4];
            #pragma unroll
            for (int i = 0; i < 4; i++)
                #pragma unroll
                for (int j = 0; j < 4; j++) cacc[i][j] = 0.f;
            for (int t4 = 0; t4 < 32; t4++) {
                float4 ev[4], vv[4];
                #pragma unroll
                for (int i = 0; i < 4; i++) ev[i] = *(const float4*)(ekb + (d0+(i<<3))*132 + (t4<<2));
                #pragma unroll
                for (int j = 0; j < 4; j++) vv[j] = *(const float4*)(vvb + (e0+(j<<3))*132 + (t4<<2));
                #pragma unroll
                for (int i = 0; i < 4; i++)
                    #pragma unroll
                    for (int j = 0; j < 4; j++) {
                        cacc[i][j] = fmaf(ev[i].x, vv[j].x, cacc[i][j]);
                        cacc[i][j] = fmaf(ev[i].y, vv[j].y, cacc[i][j]);
                        cacc[i][j] = fmaf(ev[i].z, vv[j].z, cacc[i][j]);
                        cacc[i][j] = fmaf(ev[i].w, vv[j].w, cacc[i][j]);
                    }
            }
            float* cbase = g_ctx + (((b<<2)+h)<<10);
            #pragma unroll
            for (int i = 0; i < 4; i++)
                #pragma unroll
                for (int j = 0; j < 4; j++)
                    atomicAdd(cbase + ((d0+(i<<3))<<5) + e0+(j<<3), cacc[i][j]);
        }
    }
}

// ---------------------------------------------------------------------------
// K2: per 128-token tile: q softmax(over d) * scale, O = ctx^T q, y = Wout O + b,
//     rmsnorm, store.
// smem: Qs @0 (64K) | Wo @65536 (64K) | Os @131072 (64K) | ctx @196608 (16K)
//       | bias @212992 | g2 @213504 | inv @214016 | ss @214528 (8704)
// ---------------------------------------------------------------------------
#define K2_SMEM 223232

__global__ __launch_bounds__(256,1) void out_kernel(const float* __restrict__ b_out,
                                                    const float* __restrict__ g2,
                                                    float* __restrict__ out) {
    extern __shared__ char sm[];
    float* Qs   = (float*)(sm);
    float* Wo   = (float*)(sm + 65536);
    float* Os   = (float*)(sm + 131072);
    float* ctx  = (float*)(sm + 196608);
    float* bs   = (float*)(sm + 212992);
    float* g2s  = (float*)(sm + 213504);
    float* invs = (float*)(sm + 214016);
    float* ss   = (float*)(sm + 214528);

    const int tid = threadIdx.x, tx = tid & 15, ox = tid >> 4;
    const int b = blockIdx.y; const int p0 = blockIdx.x << 7;

    float4* Qs4 = (float4*)Qs; float4* Wo4 = (float4*)Wo;
    for (int i = tid; i < 4096; i += 256) {
        int o = i >> 5, t4 = i & 31;
        Qs4[i] = *((const float4*)(g_q + (((size_t)((b<<7)+o))<<14) + p0) + t4);
    }
    for (int i = tid; i < 4096; i += 256) Wo4[i] = ((const float4*)g_WoT)[i];
    for (int i = tid; i < 4096; i += 256)
        ctx[i] = g_ctx[(b<<12)+i] / g_den[(b<<7)+(i>>5)];
    if (tid < 128) { bs[tid] = b_out[tid]; g2s[tid] = g2[tid]; }
    __syncthreads();

    // O construction: 2 threads per token, 2 heads each
    {
        const int t = tid & 127, hp = tid >> 7;
        const float qscale = 0.17677669529663688f;  // 1/sqrt(32)
        for (int hh = 0; hh < 2; hh++) {
            int h = (hp<<1) + hh;
            float qv[32]; float m = -1e30f;
            #pragma unroll
            for (int d = 0; d < 32; d++) { qv[d] = Qs[(((h<<5)+d)<<7) + t]; m = fmaxf(m, qv[d]); }
            float s = 0.f;
            #pragma unroll
            for (int d = 0; d < 32; d++) { qv[d] = __expf(qv[d]-m); s += qv[d]; }
            float r = qscale / s;
            for (int e = 0; e < 32; e++) {
                float a = 0.f;
                #pragma unroll
                for (int d = 0; d < 32; d++) a = fmaf(ctx[(((h<<5)+d)<<5)+e], qv[d], a);
                Os[(((h<<5)+e)<<7) + t] = a * r;
            }
        }
    }
    __syncthreads();

    // GEMM: y[o][t] = sum_e Wo[e][o] * Os[e][t]
    ull acc[8][4];
    #pragma unroll
    for (int oi = 0; oi < 8; oi++) { acc[oi][0]=0; acc[oi][1]=0; acc[oi][2]=0; acc[oi][3]=0; }
    const ull* OsU = (const ull*)Os;
    #pragma unroll 4
    for (int kk = 0; kk < 128; kk++) {
        float4 w0 = Wo4[(kk<<5)+(ox<<1)];
        float4 w1 = Wo4[(kk<<5)+(ox<<1)+1];
        ull xp[4];
        xp[0] = OsU[(kk<<6)+(tx<<2)];
        xp[1] = OsU[(kk<<6)+(tx<<2)+1];
        xp[2] = OsU[(kk<<6)+(tx<<2)+2];
        xp[3] = OsU[(kk<<6)+(tx<<2)+3];
        ull wp[8];
        wp[0]=pack2(w0.x,w0.x); wp[1]=pack2(w0.y,w0.y); wp[2]=pack2(w0.z,w0.z); wp[3]=pack2(w0.w,w0.w);
        wp[4]=pack2(w1.x,w1.x); wp[5]=pack2(w1.y,w1.y); wp[6]=pack2(w1.z,w1.z); wp[7]=pack2(w1.w,w1.w);
        #pragma unroll
        for (int oi = 0; oi < 8; oi++) {
            acc[oi][0] = fma2(wp[oi], xp[0], acc[oi][0]);
            acc[oi][1] = fma2(wp[oi], xp[1], acc[oi][1]);
            acc[oi][2] = fma2(wp[oi], xp[2], acc[oi][2]);
            acc[oi][3] = fma2(wp[oi], xp[3], acc[oi][3]);
        }
    }

    // epilogue: +bias, rmsnorm over channels, *g2, store
    float yb[8][8];
    #pragma unroll
    for (int oi = 0; oi < 8; oi++) {
        U8 r; r.u[0]=acc[oi][0]; r.u[1]=acc[oi][1]; r.u[2]=acc[oi][2]; r.u[3]=acc[oi][3];
        float bv = bs[(ox<<3)+oi];
        #pragma unroll
        for (int j = 0; j < 8; j++) yb[oi][j] = r.f[j] + bv;
    }
    float ps[8];
    #pragma unroll
    for (int j = 0; j < 8; j++) ps[j] = 0.f;
    #pragma unroll
    for (int oi = 0; oi < 8; oi++)
        #pragma unroll
        for (int j = 0; j < 8; j++) ps[j] = fmaf(yb[oi][j], yb[oi][j], ps[j]);
    #pragma unroll
    for (int j = 0; j < 8; j++) ss[((tx<<3)+j)*17 + ox] = ps[j];
    __syncthreads();
    if (tid < 128) {
        float s = 0.f;
        #pragma unroll
        for (int k = 0; k < 16; k++) s += ss[tid*17 + k];
        invs[tid] = SQRTC / fmaxf(sqrtf(s), 1e-12f);
    }
    __syncthreads();
    #pragma unroll
    for (int oi = 0; oi < 8; oi++) {
        int o = (ox<<3)+oi; float gv = g2s[o];
        U8 r;
        #pragma unroll
        for (int j = 0; j < 8; j++) r.f[j] = yb[oi][j] * invs[(tx<<3)+j] * gv;
        float4* dst = (float4*)(out + (((size_t)((b<<7)+o))<<14) + p0 + (tx<<3));
        dst[0]=r.v4[0]; dst[1]=r.v4[1];
    }
}

// ---------------------------------------------------------------------------
extern "C" void kernel_launch(void* const* d_in, const int* in_sizes, int n_in,
                              void* d_out, int out_size) {
    const float* x    = (const float*)d_in[0];
    const float* g1   = (const float*)d_in[1];
    const float* wqkv = (const float*)d_in[2];
    const float* wout = (const float*)d_in[3];
    const float* bout = (const float*)d_in[4];
    const float* g2   = (const float*)d_in[5];
    float* out = (float*)d_out;

    cudaFuncSetAttribute(qkv_kernel, cudaFuncAttributeMaxDynamicSharedMemorySize, K1_SMEM);
    cudaFuncSetAttribute(out_kernel, cudaFuncAttributeMaxDynamicSharedMemorySize, K2_SMEM);

    prep_kernel<<<256, 256>>>(wqkv, g1, wout);
    dim3 grid(NN/128, BB);
    qkv_kernel<<<grid, 256, K1_SMEM>>>(x);
    out_kernel<<<grid, 256, K2_SMEM>>>(bout, g2, out);
}

// round 4
// speedup vs baseline: 1.3126x; 1.3126x over previous
#include <cuda_runtime.h>
#include <cuda_fp16.h>
#include <cstdint>
#include <math.h>

#define BB 16
#define CC 128
#define NN 16384
#define SQRTC 11.313708498984761f
#define QSCALE 0.17677669529663688f
#define OSCALE 64.0f
#define OSCALE_INV 0.015625f

// ---- global scratch ----
__device__ __align__(16) __half g_Wp[3][2][128 * 136];   // qkv weights hi/lo, padded rows
__device__ __align__(16) __half g_Wop[2][128 * 136];     // out weights hi/lo
__device__ float g_ctx[BB * 4 * 32 * 32];
__device__ float g_den[BB * CC];

// W copy size in uint4: 2 planes x 128*136 halves x 2B / 16B = 4352
#define W_U4 4352

// =============================== helpers ==================================
__device__ __forceinline__ uint32_t smem_u32(const void* p) {
    uint32_t a;
    asm("{ .reg .u64 t; cvta.to.shared.u64 t, %1; cvt.u32.u64 %0, t; }" : "=r"(a) : "l"(p));
    return a;
}
__device__ __forceinline__ void ldsm4(uint32_t addr, uint32_t& r0, uint32_t& r1,
                                      uint32_t& r2, uint32_t& r3) {
    asm volatile("ldmatrix.sync.aligned.m8n8.x4.shared.b16 {%0,%1,%2,%3}, [%4];"
                 : "=r"(r0), "=r"(r1), "=r"(r2), "=r"(r3) : "r"(addr));
}
__device__ __forceinline__ void mma8(float* c, uint32_t a0, uint32_t a1, uint32_t a2,
                                     uint32_t a3, uint32_t b0, uint32_t b1) {
    asm volatile(
        "mma.sync.aligned.m16n8k16.row.col.f32.f16.f16.f32 "
        "{%0,%1,%2,%3},{%4,%5,%6,%7},{%8,%9},{%0,%1,%2,%3};"
        : "+f"(c[0]), "+f"(c[1]), "+f"(c[2]), "+f"(c[3])
        : "r"(a0), "r"(a1), "r"(a2), "r"(a3), "r"(b0), "r"(b1));
}
// one hi/lo GEMM pass: A row-major [m][k], B stored [n][k]; acc 16 x (NT2*16)
template <int KSTEPS, int NT2>
__device__ __forceinline__ void gemm_pass(float* acc, uint32_t aLane, uint32_t bLane) {
    #pragma unroll
    for (int ks = 0; ks < KSTEPS; ks++) {
        uint32_t a0, a1, a2, a3;
        ldsm4(aLane + ks * 32, a0, a1, a2, a3);
        #pragma unroll
        for (int nt = 0; nt < NT2; nt++) {
            uint32_t b0, b1, b2, b3;
            ldsm4(bLane + nt * 4352 + ks * 32, b0, b1, b2, b3);
            mma8(acc + nt * 8,     a0, a1, a2, a3, b0, b1);
            mma8(acc + nt * 8 + 4, a0, a1, a2, a3, b2, b3);
        }
    }
}
__device__ __forceinline__ uint32_t a_lane_addr(uint32_t sb, uint32_t off, int m0,
                                                int rs, int lane) {
    return sb + off + (uint32_t)(m0 + (lane & 15)) * rs + ((lane >> 4) << 4);
}
__device__ __forceinline__ uint32_t b_lane_addr(uint32_t sb, uint32_t off, int lane) {
    return sb + off + (uint32_t)((lane & 7) + ((lane & 16) >> 1)) * 272 + ((lane & 8) << 1);
}
__device__ __forceinline__ void split2(float v0, float v1, uint32_t& hi, uint32_t& lo) {
    __half h0 = __float2half_rn(v0), h1 = __float2half_rn(v1);
    float l0 = v0 - __half2float(h0), l1 = v1 - __half2float(h1);
    __half2 hh = __halves2half2(h0, h1);
    __half2 ll = __floats2half2_rn(l0, l1);
    hi = *(uint32_t*)&hh; lo = *(uint32_t*)&ll;
}

// =============================== prep ======================================
__global__ void prep_kernel(const float* __restrict__ wqkv, const float* __restrict__ g1,
                            const float* __restrict__ wout) {
    int i = blockIdx.x * 256 + threadIdx.x;   // 65536
    if (i < 49152) {
        int g = i >> 14, r = i & 16383, o = r >> 7, c = r & 127;
        float v = wqkv[((g << 7) + o) * CC + c] * g1[c] * SQRTC;
        __half h = __float2half_rn(v);
        g_Wp[g][0][o * 136 + c] = h;
        g_Wp[g][1][o * 136 + c] = __float2half_rn(v - __half2float(h));
    } else {
        int j = i - 49152;
        int o = j >> 7, e = j & 127;
        float v = wout[(o << 7) + e];
        __half h = __float2half_rn(v);
        g_Wop[0][o * 136 + e] = h;
        g_Wop[1][o * 136 + e] = __float2half_rn(v - __half2float(h));
    }
    if (i < BB * 4096) g_ctx[i] = 0.f;
    if (i < BB * CC)   g_den[i] = 0.f;
}

// =============================== K1 =======================================
// regions (bytes): WH 0 | WL 34816 | XH 69632 | XL 104448 | EH 139264 | EL 174080
//                  Xs fp32 overlays 139264..204800 | inv @208896
#define K1_WH   0u
#define K1_WL   34816u
#define K1_XH   69632u
#define K1_XL   104448u
#define K1_EH   139264u
#define K1_EL   174080u
#define K1_XS   139264u
#define K1_INV  208896u
#define K1_SMEM 209920

__global__ __launch_bounds__(256, 1) void qkv_kernel(const float* __restrict__ x) {
    extern __shared__ char sm[];
    const uint32_t sb = smem_u32(sm);
    const int tid = threadIdx.x, lane = tid & 31, w = tid >> 5;
    const int b = blockIdx.y, p0 = blockIdx.x << 7;
    float* Xs  = (float*)(sm + K1_XS);
    float* inv = (float*)(sm + K1_INV);

    // phase 0: load x tile + Wk (hi+lo contiguous)
    {
        float4* Xs4 = (float4*)Xs;
        const float* xb = x + (((size_t)b) << 21) + p0;
        for (int i = tid; i < 4096; i += 256) {
            int c = i >> 5, t4 = i & 31;
            Xs4[i] = *((const float4*)(xb + ((size_t)c << 14)) + t4);
        }
        const uint4* wsrc = (const uint4*)g_Wp[1][0];
        uint4* wdst = (uint4*)(sm + K1_WH);
        for (int i = tid; i < W_U4; i += 256) wdst[i] = wsrc[i];
    }
    __syncthreads();
    if (tid < 128) {
        float s = 0.f;
        #pragma unroll 16
        for (int c = 0; c < 128; c++) { float v = Xs[(c << 7) + tid]; s = fmaf(v, v, s); }
        inv[tid] = 1.0f / fmaxf(sqrtf(s), 1e-12f);
    }
    __syncthreads();
    // build X operand [t][c] hi/lo (inv folded)
    {
        const int t = tid >> 1, c0 = (tid & 1) << 6;
        const float it = inv[t];
        char* ph = sm + K1_XH + t * 272;
        char* pl = sm + K1_XL + t * 272;
        #pragma unroll 8
        for (int j = 0; j < 32; j++) {
            int c = c0 + (j << 1);
            float v0 = Xs[(c << 7) + t] * it;
            float v1 = Xs[((c + 1) << 7) + t] * it;
            uint32_t hh, ll; split2(v0, v1, hh, ll);
            *(uint32_t*)(ph + c * 2) = hh;
            *(uint32_t*)(pl + c * 2) = ll;
        }
    }
    __syncthreads();

    const int m0 = w << 4;
    const int gp = lane >> 2, tq = (lane & 3) << 1;
    const uint32_t bXH = b_lane_addr(sb, K1_XH, lane);
    const uint32_t bXL = b_lane_addr(sb, K1_XL, lane);

    // ---- GEMM k ----
    float acc[64];
    #pragma unroll
    for (int i = 0; i < 64; i++) acc[i] = 0.f;
    {
        uint32_t aH = a_lane_addr(sb, K1_WH, m0, 272, lane);
        uint32_t aL = a_lane_addr(sb, K1_WL, m0, 272, lane);
        gemm_pass<8, 8>(acc, aH, bXH);
        gemm_pass<8, 8>(acc, aH, bXL);
        gemm_pass<8, 8>(acc, aL, bXH);
    }
    // epilogue k: exp -> E hi/lo, den atomics
    {
        const int r0 = m0 + gp, r1 = r0 + 8;
        float d0 = 0.f, d1 = 0.f;
        #pragma unroll
        for (int nt = 0; nt < 8; nt++) {
            #pragma unroll
            for (int s2 = 0; s2 < 2; s2++) {
                int cb = (nt << 4) + (s2 << 3) + tq;
                const float* a4 = acc + (nt << 3) + (s2 << 2);
                float e00 = __expf(a4[0]), e01 = __expf(a4[1]);
                float e10 = __expf(a4[2]), e11 = __expf(a4[3]);
                d0 += e00 + e01; d1 += e10 + e11;
                uint32_t hh, ll;
                split2(e00, e01, hh, ll);
                *(uint32_t*)(sm + K1_EH + r0 * 272 + cb * 2) = hh;
                *(uint32_t*)(sm + K1_EL + r0 * 272 + cb * 2) = ll;
                split2(e10, e11, hh, ll);
                *(uint32_t*)(sm + K1_EH + r1 * 272 + cb * 2) = hh;
                *(uint32_t*)(sm + K1_EL + r1 * 272 + cb * 2) = ll;
            }
        }
        d0 += __shfl_xor_sync(0xffffffffu, d0, 1);
        d0 += __shfl_xor_sync(0xffffffffu, d0, 2);
        d1 += __shfl_xor_sync(0xffffffffu, d1, 1);
        d1 += __shfl_xor_sync(0xffffffffu, d1, 2);
        if ((lane & 3) == 0) {
            atomicAdd(&g_den[(b << 7) + r0], d0);
            atomicAdd(&g_den[(b << 7) + r1], d1);
        }
    }
    __syncthreads();
    // load Wv
    {
        const uint4* wsrc = (const uint4*)g_Wp[2][0];
        uint4* wdst = (uint4*)(sm + K1_WH);
        for (int i = tid; i < W_U4; i += 256) wdst[i] = wsrc[i];
    }
    __syncthreads();
    // ---- GEMM v ----
    #pragma unroll
    for (int i = 0; i < 64; i++) acc[i] = 0.f;
    {
        uint32_t aH = a_lane_addr(sb, K1_WH, m0, 272, lane);
        uint32_t aL = a_lane_addr(sb, K1_WL, m0, 272, lane);
        gemm_pass<8, 8>(acc, aH, bXH);
        gemm_pass<8, 8>(acc, aH, bXL);
        gemm_pass<8, 8>(acc, aL, bXH);
    }
    __syncthreads();   // all X reads done; V overwrites X region
    {
        const int r0 = m0 + gp, r1 = r0 + 8;
        #pragma unroll
        for (int nt = 0; nt < 8; nt++) {
            #pragma unroll
            for (int s2 = 0; s2 < 2; s2++) {
                int cb = (nt << 4) + (s2 << 3) + tq;
                const float* a4 = acc + (nt << 3) + (s2 << 2);
                uint32_t hh, ll;
                split2(a4[0], a4[1], hh, ll);
                *(uint32_t*)(sm + K1_XH + r0 * 272 + cb * 2) = hh;
                *(uint32_t*)(sm + K1_XL + r0 * 272 + cb * 2) = ll;
                split2(a4[2], a4[3], hh, ll);
                *(uint32_t*)(sm + K1_XH + r1 * 272 + cb * 2) = hh;
                *(uint32_t*)(sm + K1_XL + r1 * 272 + cb * 2) = ll;
            }
        }
    }
    __syncthreads();
    // ---- gram: ctx[d][e] += sum_t Ek[d][t] * V[e][t]  (per-head diag blocks) ----
    {
        const int h = w >> 1;
        float acc16[16];
        #pragma unroll
        for (int i = 0; i < 16; i++) acc16[i] = 0.f;
        uint32_t aH = a_lane_addr(sb, K1_EH, m0, 272, lane);
        uint32_t aL = a_lane_addr(sb, K1_EL, m0, 272, lane);
        uint32_t bH = b_lane_addr(sb, K1_XH + h * 8704u, lane);
        uint32_t bL = b_lane_addr(sb, K1_XL + h * 8704u, lane);
        gemm_pass<8, 2>(acc16, aH, bH);
        gemm_pass<8, 2>(acc16, aH, bL);
        gemm_pass<8, 2>(acc16, aL, bH);

        const int dl0 = (m0 + gp) & 31, dl1 = dl0 + 8;
        float* cbase = g_ctx + (((b << 2) + h) << 10);
        #pragma unroll
        for (int nt = 0; nt < 2; nt++) {
            #pragma unroll
            for (int s2 = 0; s2 < 2; s2++) {
                int cb = (nt << 4) + (s2 << 3) + tq;
                const float* a4 = acc16 + (nt << 3) + (s2 << 2);
                atomicAdd(cbase + (dl0 << 5) + cb,     a4[0]);
                atomicAdd(cbase + (dl0 << 5) + cb + 1, a4[1]);
                atomicAdd(cbase + (dl1 << 5) + cb,     a4[2]);
                atomicAdd(cbase + (dl1 << 5) + cb + 1, a4[3]);
            }
        }
    }
}

// =============================== K2 =======================================
// regions: 0: WqH/BpH/Ys | 34816: WqL/BpL | 69632: XH/WoH | 104448: XL/WoL
//          139264: Xs/Qlog/OBH | 174080: OBL
//          208896: ctxAH | 219136: ctxAL | 229376: bias | 229888: g2
//          230400: inv | 230912: invs
#define K2_R0   0u
#define K2_R0L  34816u
#define K2_R1   69632u
#define K2_R1L  104448u
#define K2_R2   139264u
#define K2_R2L  174080u
#define K2_CTXH 208896u
#define K2_CTXL 219136u
#define K2_BIAS 229376u
#define K2_G2   229888u
#define K2_INV  230400u
#define K2_INVS 230912u
#define K2_SMEM 231424

__global__ __launch_bounds__(256, 1) void out_kernel(const float* __restrict__ x,
                                                     const float* __restrict__ b_out,
                                                     const float* __restrict__ g2,
                                                     float* __restrict__ out) {
    extern __shared__ char sm[];
    const uint32_t sb = smem_u32(sm);
    const int tid = threadIdx.x, lane = tid & 31, w = tid >> 5;
    const int b = blockIdx.y, p0 = blockIdx.x << 7;
    float* Xs   = (float*)(sm + K2_R2);
    float* Qlog = (float*)(sm + K2_R2);      // stride 132
    float* Ys   = (float*)(sm + K2_R0);      // stride 132
    float* inv  = (float*)(sm + K2_INV);
    float* invs = (float*)(sm + K2_INVS);
    float* bs   = (float*)(sm + K2_BIAS);
    float* g2s  = (float*)(sm + K2_G2);

    // phase 0: x tile + Wq
    {
        float4* Xs4 = (float4*)Xs;
        const float* xb = x + (((size_t)b) << 21) + p0;
        for (int i = tid; i < 4096; i += 256) {
            int c = i >> 5, t4 = i & 31;
            Xs4[i] = *((const float4*)(xb + ((size_t)c << 14)) + t4);
        }
        const uint4* wsrc = (const uint4*)g_Wp[0][0];
        uint4* wdst = (uint4*)(sm + K2_R0);
        for (int i = tid; i < W_U4; i += 256) wdst[i] = wsrc[i];
    }
    __syncthreads();
    if (tid < 128) {
        float s = 0.f;
        #pragma unroll 16
        for (int c = 0; c < 128; c++) { float v = Xs[(c << 7) + tid]; s = fmaf(v, v, s); }
        inv[tid] = 1.0f / fmaxf(sqrtf(s), 1e-12f);
    }
    __syncthreads();
    {
        const int t = tid >> 1, c0 = (tid & 1) << 6;
        const float it = inv[t];
        char* ph = sm + K2_R1 + t * 272;
        char* pl = sm + K2_R1L + t * 272;
        #pragma unroll 8
        for (int j = 0; j < 32; j++) {
            int c = c0 + (j << 1);
            float v0 = Xs[(c << 7) + t] * it;
            float v1 = Xs[((c + 1) << 7) + t] * it;
            uint32_t hh, ll; split2(v0, v1, hh, ll);
            *(uint32_t*)(ph + c * 2) = hh;
            *(uint32_t*)(pl + c * 2) = ll;
        }
    }
    __syncthreads();

    const int m0 = w << 4;
    const int gp = lane >> 2, tq = (lane & 3) << 1;

    // ---- GEMM q ----
    float acc[64];
    #pragma unroll
    for (int i = 0; i < 64; i++) acc[i] = 0.f;
    {
        uint32_t aH = a_lane_addr(sb, K2_R0, m0, 272, lane);
        uint32_t aL = a_lane_addr(sb, K2_R0L, m0, 272, lane);
        uint32_t bH = b_lane_addr(sb, K2_R1, lane);
        uint32_t bL = b_lane_addr(sb, K2_R1L, lane);
        gemm_pass<8, 8>(acc, aH, bH);
        gemm_pass<8, 8>(acc, aH, bL);
        gemm_pass<8, 8>(acc, aL, bH);
    }
    // epilogue: q logits fp32 to smem (overwrites Xs)
    {
        const int r0 = m0 + gp, r1 = r0 + 8;
        #pragma unroll
        for (int nt = 0; nt < 8; nt++) {
            #pragma unroll
            for (int s2 = 0; s2 < 2; s2++) {
                int cb = (nt << 4) + (s2 << 3) + tq;
                const float* a4 = acc + (nt << 3) + (s2 << 2);
                *(float2*)(Qlog + r0 * 132 + cb) = make_float2(a4[0], a4[1]);
                *(float2*)(Qlog + r1 * 132 + cb) = make_float2(a4[2], a4[3]);
            }
        }
    }
    __syncthreads();

    // phase S: softmax (tid<128) writes Bp; others build ctxA + load Wo + bias/g2
    if (tid < 128) {
        const int t = tid;
        char* ph = sm + K2_R0 + t * 272;
        char* pl = sm + K2_R0L + t * 272;
        #pragma unroll
        for (int h = 0; h < 4; h++) {
            float pv[32];
            float m = -1e30f;
            #pragma unroll 8
            for (int d = 0; d < 32; d++) {
                pv[d] = Qlog[((h << 5) + d) * 132 + t];
                m = fmaxf(m, pv[d]);
            }
            float s = 0.f;
            #pragma unroll 8
            for (int d = 0; d < 32; d++) { pv[d] = __expf(pv[d] - m); s += pv[d]; }
            float rcp = QSCALE / s;
            #pragma unroll 8
            for (int d2 = 0; d2 < 16; d2++) {
                int c = (h << 5) + (d2 << 1);
                uint32_t hh, ll; split2(pv[d2 << 1] * rcp, pv[(d2 << 1) + 1] * rcp, hh, ll);
                *(uint32_t*)(ph + c * 2) = hh;
                *(uint32_t*)(pl + c * 2) = ll;
            }
        }
    } else {
        const int t2 = tid - 128;
        // ctxA[h][e][d] = ctx[d][e]/den  (hi/lo, stride 40 halfs)
        for (int j = 0; j < 32; j++) {
            int v = t2 + (j << 7);
            int h = v >> 10, e = (v >> 5) & 31, d = v & 31;
            float c = g_ctx[(((b << 2) + h) << 10) + (d << 5) + e]
                    / g_den[(b << 7) + (h << 5) + d];
            __half hh = __float2half_rn(c);
            float lo = c - __half2float(hh);
            *(__half*)(sm + K2_CTXH + h * 2560 + e * 80 + d * 2) = hh;
            *(__half*)(sm + K2_CTXL + h * 2560 + e * 80 + d * 2) = __float2half_rn(lo);
        }
        // Wo -> R1 (hi+lo contiguous)
        const uint4* wsrc = (const uint4*)g_Wop[0];
        uint4* wdst = (uint4*)(sm + K2_R1);
        for (int i = t2; i < W_U4; i += 128) wdst[i] = wsrc[i];
        if (t2 < 128) { bs[t2] = b_out[t2]; g2s[t2] = g2[t2]; }
    }
    __syncthreads();

    // ---- GEMM ctx-apply: O[e][t] = sum_d ctxA[e][d] * p[d][t] ----
    {
        const int h = w >> 1, m0l = (w & 1) << 4;
        #pragma unroll
        for (int i = 0; i < 64; i++) acc[i] = 0.f;
        uint32_t aH = sb + K2_CTXH + h * 2560u + (uint32_t)(m0l + (lane & 15)) * 80 + ((lane >> 4) << 4);
        uint32_t aL = aH + (K2_CTXL - K2_CTXH);
        uint32_t bH = b_lane_addr(sb, K2_R0 + h * 64u, lane);
        uint32_t bL = b_lane_addr(sb, K2_R0L + h * 64u, lane);
        gemm_pass<2, 8>(acc, aH, bH);
        gemm_pass<2, 8>(acc, aH, bL);
        gemm_pass<2, 8>(acc, aL, bH);
        __syncthreads();   // Bp reads done; Qlog readers done -> OB can overwrite R2
        const int eg0 = (h << 5) + m0l + gp, eg1 = eg0 + 8;
        #pragma unroll
        for (int nt = 0; nt < 8; nt++) {
            #pragma unroll
            for (int s2 = 0; s2 < 2; s2++) {
                int cb = (nt << 4) + (s2 << 3) + tq;
                const float* a4 = acc + (nt << 3) + (s2 << 2);
                #pragma unroll
                for (int q = 0; q < 4; q++) {
                    int tcol = cb + (q & 1);
                    int eg = (q < 2) ? eg0 : eg1;
                    float sv = a4[q] * OSCALE;
                    __half hh = __float2half_rn(sv);
                    *(__half*)(sm + K2_R2 + tcol * 272 + eg * 2) = hh;
                    *(__half*)(sm + K2_R2L + tcol * 272 + eg * 2) =
                        __float2half_rn(sv - __half2float(hh));
                }
            }
        }
    }
    __syncthreads();

    // ---- GEMM out: y[o][t] = sum_e Wo[o][e] * OB[t][e] ----
    #pragma unroll
    for (int i = 0; i < 64; i++) acc[i] = 0.f;
    {
        uint32_t aH = a_lane_addr(sb, K2_R1, m0, 272, lane);
        uint32_t aL = a_lane_addr(sb, K2_R1L, m0, 272, lane);
        uint32_t bH = b_lane_addr(sb, K2_R2, lane);
        uint32_t bL = b_lane_addr(sb, K2_R2L, lane);
        gemm_pass<8, 8>(acc, aH, bH);
        gemm_pass<8, 8>(acc, aH, bL);
        gemm_pass<8, 8>(acc, aL, bH);
    }
    __syncthreads();   // Bp region (R0) reads fully done -> Ys overwrite
    {
        const int r0 = m0 + gp, r1 = r0 + 8;
        const float b0v = bs[r0], b1v = bs[r1];
        #pragma unroll
        for (int nt = 0; nt < 8; nt++) {
            #pragma unroll
            for (int s2 = 0; s2 < 2; s2++) {
                int cb = (nt << 4) + (s2 << 3) + tq;
                const float* a4 = acc + (nt << 3) + (s2 << 2);
                *(float2*)(Ys + r0 * 132 + cb) =
                    make_float2(a4[0] * OSCALE_INV + b0v, a4[1] * OSCALE_INV + b0v);
                *(float2*)(Ys + r1 * 132 + cb) =
                    make_float2(a4[2] * OSCALE_INV + b1v, a4[3] * OSCALE_INV + b1v);
            }
        }
    }
    __syncthreads();
    if (tid < 128) {
        float s = 0.f;
        #pragma unroll 16
        for (int o = 0; o < 128; o++) { float v = Ys[o * 132 + tid]; s = fmaf(v, v, s); }
        invs[tid] = SQRTC / fmaxf(sqrtf(s), 1e-12f);
    }
    __syncthreads();
    {
        const int to = tid & 127, oh = (tid >> 7) << 6;
        const float iv = invs[to];
        float* ob = out + (((size_t)b) << 21) + p0 + to;
        #pragma unroll 8
        for (int j = 0; j < 64; j++) {
            int o = oh + j;
            ob[(size_t)o << 14] = Ys[o * 132 + to] * iv * g2s[o];
        }
    }
}

// ---------------------------------------------------------------------------
extern "C" void kernel_launch(void* const* d_in, const int* in_sizes, int n_in,
                              void* d_out, int out_size) {
    const float* x    = (const float*)d_in[0];
    const float* g1   = (const float*)d_in[1];
    const float* wqkv = (const float*)d_in[2];
    const float* wout = (const float*)d_in[3];
    const float* bout = (const float*)d_in[4];
    const float* g2   = (const float*)d_in[5];
    float* out = (float*)d_out;

    cudaFuncSetAttribute(qkv_kernel, cudaFuncAttributeMaxDynamicSharedMemorySize, K1_SMEM);
    cudaFuncSetAttribute(out_kernel, cudaFuncAttributeMaxDynamicSharedMemorySize, K2_SMEM);

    prep_kernel<<<256, 256>>>(wqkv, g1, wout);
    dim3 grid(NN / 128, BB);
    qkv_kernel<<<grid, 256, K1_SMEM>>>(x);
    out_kernel<<<grid, 256, K2_SMEM>>>(x, bout, g2, out);
}

// round 5
// speedup vs baseline: 1.9719x; 1.5023x over previous
#include <cuda_runtime.h>
#include <cuda_fp16.h>
#include <cstdint>
#include <math.h>

#define BB 16
#define CC 128
#define NN 16384
#define SQRTC 11.313708498984761f
#define QSCALE 0.17677669529663688f

// ---- global scratch ----
__device__ __align__(16) __half g_W16[3][128 * 136];   // qkv weights fp16, padded rows
__device__ __align__(16) __half g_Wo16[128 * 136];     // out weights fp16
__device__ float g_ctx[BB * 4 * 32 * 32];
__device__ float g_den[BB * CC];

// =============================== helpers ==================================
__device__ __forceinline__ uint32_t smem_u32(const void* p) {
    uint32_t a;
    asm("{ .reg .u64 t; cvta.to.shared.u64 t, %1; cvt.u32.u64 %0, t; }" : "=r"(a) : "l"(p));
    return a;
}
__device__ __forceinline__ void ldsm4(uint32_t addr, uint32_t& r0, uint32_t& r1,
                                      uint32_t& r2, uint32_t& r3) {
    asm volatile("ldmatrix.sync.aligned.m8n8.x4.shared.b16 {%0,%1,%2,%3}, [%4];"
                 : "=r"(r0), "=r"(r1), "=r"(r2), "=r"(r3) : "r"(addr));
}
__device__ __forceinline__ void mma8(float* c, uint32_t a0, uint32_t a1, uint32_t a2,
                                     uint32_t a3, uint32_t b0, uint32_t b1) {
    asm volatile(
        "mma.sync.aligned.m16n8k16.row.col.f32.f16.f16.f32 "
        "{%0,%1,%2,%3},{%4,%5,%6,%7},{%8,%9},{%0,%1,%2,%3};"
        : "+f"(c[0]), "+f"(c[1]), "+f"(c[2]), "+f"(c[3])
        : "r"(a0), "r"(a1), "r"(a2), "r"(a3), "r"(b0), "r"(b1));
}
// GEMM pass: A row-major [m][k] (stride 272B), B stored [n][k] (stride 272B)
template <int KSTEPS, int NT2>
__device__ __forceinline__ void gemm_pass(float* acc, uint32_t aLane, uint32_t bLane) {
    #pragma unroll
    for (int ks = 0; ks < KSTEPS; ks++) {
        uint32_t a0, a1, a2, a3;
        ldsm4(aLane + ks * 32, a0, a1, a2, a3);
        #pragma unroll
        for (int nt = 0; nt < NT2; nt++) {
            uint32_t b0, b1, b2, b3;
            ldsm4(bLane + nt * 4352 + ks * 32, b0, b1, b2, b3);
            mma8(acc + nt * 8,     a0, a1, a2, a3, b0, b1);
            mma8(acc + nt * 8 + 4, a0, a1, a2, a3, b2, b3);
        }
    }
}
__device__ __forceinline__ uint32_t a_lane_addr(uint32_t sb, uint32_t off, int m0,
                                                int rs, int lane) {
    return sb + off + (uint32_t)(m0 + (lane & 15)) * rs + ((lane >> 4) << 4);
}
__device__ __forceinline__ uint32_t b_lane_addr(uint32_t sb, uint32_t off, int lane) {
    return sb + off + (uint32_t)((lane & 7) + ((lane & 16) >> 1)) * 272 + ((lane & 8) << 1);
}

// =============================== prep ======================================
__global__ void prep_kernel(const float* __restrict__ wqkv, const float* __restrict__ g1,
                            const float* __restrict__ wout) {
    int i = blockIdx.x * 256 + threadIdx.x;   // 65536
    if (i < 49152) {
        int g = i >> 14, r = i & 16383, o = r >> 7, c = r & 127;
        float v = wqkv[((g << 7) + o) * CC + c] * g1[c] * SQRTC;
        g_W16[g][o * 136 + c] = __float2half_rn(v);
    } else {
        int j = i - 49152;
        int o = j >> 7, e = j & 127;
        g_Wo16[o * 136 + e] = __float2half_rn(wout[(o << 7) + e]);
    }
    if (i < BB * 4096) g_ctx[i] = 0.f;
    if (i < BB * CC)   g_den[i] = 0.f;
}

// =============================== K1 =======================================
// regions: Wk@0 | Wv@34816 | X@69632 | Xs fp32 @104448 (E@104448, V@139264 overlay)
//          inv @174080
#define K1_WK   0u
#define K1_WV   34816u
#define K1_X    69632u
#define K1_XS   104448u
#define K1_E    104448u
#define K1_V    139264u
#define K1_INV  174080u
#define K1_SMEM 174592

__global__ __launch_bounds__(256, 1) void qkv_kernel(const float* __restrict__ x) {
    extern __shared__ char sm[];
    const uint32_t sb = smem_u32(sm);
    const int tid = threadIdx.x, lane = tid & 31, w = tid >> 5;
    const int b = blockIdx.y, p0 = blockIdx.x << 7;
    float* Xs  = (float*)(sm + K1_XS);
    float* inv = (float*)(sm + K1_INV);

    // phase 0: load x tile + Wk&Wv (contiguous 69632B = 4352 uint4)
    {
        float4* Xs4 = (float4*)Xs;
        const float* xb = x + (((size_t)b) << 21) + p0;
        for (int i = tid; i < 4096; i += 256) {
            int c = i >> 5, t4 = i & 31;
            Xs4[i] = *((const float4*)(xb + ((size_t)c << 14)) + t4);
        }
        const uint4* wsrc = (const uint4*)g_W16[1];
        uint4* wdst = (uint4*)(sm + K1_WK);
        for (int i = tid; i < 4352; i += 256) wdst[i] = wsrc[i];
    }
    __syncthreads();
    if (tid < 128) {
        float s = 0.f;
        #pragma unroll 16
        for (int c = 0; c < 128; c++) { float v = Xs[(c << 7) + tid]; s = fmaf(v, v, s); }
        inv[tid] = 1.0f / fmaxf(sqrtf(s), 1e-12f);
    }
    __syncthreads();
    // build X operand [t][c] fp16 (inv folded)
    {
        const int t = tid >> 1, c0 = (tid & 1) << 6;
        const float it = inv[t];
        char* px = sm + K1_X + t * 272;
        #pragma unroll 8
        for (int j = 0; j < 32; j++) {
            int c = c0 + (j << 1);
            __half2 h = __floats2half2_rn(Xs[(c << 7) + t] * it, Xs[((c + 1) << 7) + t] * it);
            *(uint32_t*)(px + c * 2) = *(uint32_t*)&h;
        }
    }
    __syncthreads();

    const int m0 = w << 4;
    const int gp = lane >> 2, tq = (lane & 3) << 1;
    const uint32_t bX = b_lane_addr(sb, K1_X, lane);

    // ---- GEMM k ----
    float acc[64];
    #pragma unroll
    for (int i = 0; i < 64; i++) acc[i] = 0.f;
    gemm_pass<8, 8>(acc, a_lane_addr(sb, K1_WK, m0, 272, lane), bX);

    // epilogue k: exp -> E, den atomics (Xs dead -> E overlay safe)
    {
        const int r0 = m0 + gp, r1 = r0 + 8;
        float d0 = 0.f, d1 = 0.f;
        #pragma unroll
        for (int nt = 0; nt < 8; nt++) {
            #pragma unroll
            for (int s2 = 0; s2 < 2; s2++) {
                int cb = (nt << 4) + (s2 << 3) + tq;
                const float* a4 = acc + (nt << 3) + (s2 << 2);
                float e00 = __expf(a4[0]), e01 = __expf(a4[1]);
                float e10 = __expf(a4[2]), e11 = __expf(a4[3]);
                d0 += e00 + e01; d1 += e10 + e11;
                __half2 h0 = __floats2half2_rn(e00, e01);
                __half2 h1 = __floats2half2_rn(e10, e11);
                *(uint32_t*)(sm + K1_E + r0 * 272 + cb * 2) = *(uint32_t*)&h0;
                *(uint32_t*)(sm + K1_E + r1 * 272 + cb * 2) = *(uint32_t*)&h1;
            }
        }
        d0 += __shfl_xor_sync(0xffffffffu, d0, 1);
        d0 += __shfl_xor_sync(0xffffffffu, d0, 2);
        d1 += __shfl_xor_sync(0xffffffffu, d1, 1);
        d1 += __shfl_xor_sync(0xffffffffu, d1, 2);
        if ((lane & 3) == 0) {
            atomicAdd(&g_den[(b << 7) + r0], d0);
            atomicAdd(&g_den[(b << 7) + r1], d1);
        }
    }

    // ---- GEMM v (X unchanged, no barrier needed) ----
    #pragma unroll
    for (int i = 0; i < 64; i++) acc[i] = 0.f;
    gemm_pass<8, 8>(acc, a_lane_addr(sb, K1_WV, m0, 272, lane), bX);
    {
        const int r0 = m0 + gp, r1 = r0 + 8;
        #pragma unroll
        for (int nt = 0; nt < 8; nt++) {
            #pragma unroll
            for (int s2 = 0; s2 < 2; s2++) {
                int cb = (nt << 4) + (s2 << 3) + tq;
                const float* a4 = acc + (nt << 3) + (s2 << 2);
                __half2 h0 = __floats2half2_rn(a4[0], a4[1]);
                __half2 h1 = __floats2half2_rn(a4[2], a4[3]);
                *(uint32_t*)(sm + K1_V + r0 * 272 + cb * 2) = *(uint32_t*)&h0;
                *(uint32_t*)(sm + K1_V + r1 * 272 + cb * 2) = *(uint32_t*)&h1;
            }
        }
    }
    __syncthreads();

    // ---- gram: ctx[d][e] += sum_t E[d][t] * V[e][t]  (per-head diag blocks) ----
    {
        const int h = w >> 1;
        float acc16[16];
        #pragma unroll
        for (int i = 0; i < 16; i++) acc16[i] = 0.f;
        gemm_pass<8, 2>(acc16, a_lane_addr(sb, K1_E, m0, 272, lane),
                        b_lane_addr(sb, K1_V + h * 8704u, lane));

        const int dl0 = (m0 + gp) & 31, dl1 = dl0 + 8;
        float* cbase = g_ctx + (((b << 2) + h) << 10);
        #pragma unroll
        for (int nt = 0; nt < 2; nt++) {
            #pragma unroll
            for (int s2 = 0; s2 < 2; s2++) {
                int cb = (nt << 4) + (s2 << 3) + tq;
                const float* a4 = acc16 + (nt << 3) + (s2 << 2);
                atomicAdd(cbase + (dl0 << 5) + cb,     a4[0]);
                atomicAdd(cbase + (dl0 << 5) + cb + 1, a4[1]);
                atomicAdd(cbase + (dl1 << 5) + cb,     a4[2]);
                atomicAdd(cbase + (dl1 << 5) + cb + 1, a4[3]);
            }
        }
    }
}

// =============================== K2 =======================================
// regions: Wq@0 (Bp overlay) | X@34816 (Wo overlay) | Xs@69632 (QL/OB/Ys overlay)
//          ctxA@137216 | bias@147456 | g2@147968 | inv@148480 | invs@148992
#define K2_WQ   0u
#define K2_BP   0u
#define K2_X    34816u
#define K2_WO   34816u
#define K2_XS   69632u
#define K2_QL   69632u
#define K2_OB   69632u
#define K2_YS   69632u
#define K2_CTX  137216u
#define K2_BIAS 147456u
#define K2_G2   147968u
#define K2_INV  148480u
#define K2_INVS 148992u
#define K2_SMEM 149504

__global__ __launch_bounds__(256, 1) void out_kernel(const float* __restrict__ x,
                                                     const float* __restrict__ b_out,
                                                     const float* __restrict__ g2,
                                                     float* __restrict__ out) {
    extern __shared__ char sm[];
    const uint32_t sb = smem_u32(sm);
    const int tid = threadIdx.x, lane = tid & 31, w = tid >> 5;
    const int b = blockIdx.y, p0 = blockIdx.x << 7;
    float* Xs   = (float*)(sm + K2_XS);
    float* QL   = (float*)(sm + K2_QL);      // stride 132
    float* Ys   = (float*)(sm + K2_YS);      // stride 132
    float* inv  = (float*)(sm + K2_INV);
    float* invs = (float*)(sm + K2_INVS);
    float* bs   = (float*)(sm + K2_BIAS);
    float* g2s  = (float*)(sm + K2_G2);

    // phase 0: x tile + Wq
    {
        float4* Xs4 = (float4*)Xs;
        const float* xb = x + (((size_t)b) << 21) + p0;
        for (int i = tid; i < 4096; i += 256) {
            int c = i >> 5, t4 = i & 31;
            Xs4[i] = *((const float4*)(xb + ((size_t)c << 14)) + t4);
        }
        const uint4* wsrc = (const uint4*)g_W16[0];
        uint4* wdst = (uint4*)(sm + K2_WQ);
        for (int i = tid; i < 2176; i += 256) wdst[i] = wsrc[i];
    }
    __syncthreads();
    if (tid < 128) {
        float s = 0.f;
        #pragma unroll 16
        for (int c = 0; c < 128; c++) { float v = Xs[(c << 7) + tid]; s = fmaf(v, v, s); }
        inv[tid] = 1.0f / fmaxf(sqrtf(s), 1e-12f);
    }
    __syncthreads();
    {
        const int t = tid >> 1, c0 = (tid & 1) << 6;
        const float it = inv[t];
        char* px = sm + K2_X + t * 272;
        #pragma unroll 8
        for (int j = 0; j < 32; j++) {
            int c = c0 + (j << 1);
            __half2 h = __floats2half2_rn(Xs[(c << 7) + t] * it, Xs[((c + 1) << 7) + t] * it);
            *(uint32_t*)(px + c * 2) = *(uint32_t*)&h;
        }
    }
    __syncthreads();

    const int m0 = w << 4;
    const int gp = lane >> 2, tq = (lane & 3) << 1;

    // ---- GEMM q ----
    float acc[64];
    #pragma unroll
    for (int i = 0; i < 64; i++) acc[i] = 0.f;
    gemm_pass<8, 8>(acc, a_lane_addr(sb, K2_WQ, m0, 272, lane),
                    b_lane_addr(sb, K2_X, lane));
    // epilogue: q logits fp32 -> QL (Xs dead)
    {
        const int r0 = m0 + gp, r1 = r0 + 8;
        #pragma unroll
        for (int nt = 0; nt < 8; nt++) {
            #pragma unroll
            for (int s2 = 0; s2 < 2; s2++) {
                int cb = (nt << 4) + (s2 << 3) + tq;
                const float* a4 = acc + (nt << 3) + (s2 << 2);
                *(float2*)(QL + r0 * 132 + cb) = make_float2(a4[0], a4[1]);
                *(float2*)(QL + r1 * 132 + cb) = make_float2(a4[2], a4[3]);
            }
        }
    }
    __syncthreads();

    // phase S: tid<128 softmax -> Bp (over Wq, dead); tid>=128 ctxA + Wo + bias/g2
    if (tid < 128) {
        const int t = tid;
        char* pb = sm + K2_BP + t * 272;
        #pragma unroll
        for (int h = 0; h < 4; h++) {
            float pv[32];
            float m = -1e30f;
            #pragma unroll 8
            for (int d = 0; d < 32; d++) {
                pv[d] = QL[((h << 5) + d) * 132 + t];
                m = fmaxf(m, pv[d]);
            }
            float s = 0.f;
            #pragma unroll 8
            for (int d = 0; d < 32; d++) { pv[d] = __expf(pv[d] - m); s += pv[d]; }
            float rcp = QSCALE / s;
            #pragma unroll 8
            for (int d2 = 0; d2 < 16; d2++) {
                int c = (h << 5) + (d2 << 1);
                __half2 hh = __floats2half2_rn(pv[d2 << 1] * rcp, pv[(d2 << 1) + 1] * rcp);
                *(uint32_t*)(pb + c * 2) = *(uint32_t*)&hh;
            }
        }
    } else {
        const int t2 = tid - 128;
        // ctxA[h][e][d] = ctx[d][e]/den (stride 40 halfs per e-row)
        for (int j = 0; j < 32; j++) {
            int v = t2 + (j << 7);
            int h = v >> 10, e = (v >> 5) & 31, d = v & 31;
            float c = g_ctx[(((b << 2) + h) << 10) + (d << 5) + e]
                    / g_den[(b << 7) + (h << 5) + d];
            *(__half*)(sm + K2_CTX + h * 2560 + e * 80 + d * 2) = __float2half_rn(c);
        }
        // Wo -> X region (dead)
        const uint4* wsrc = (const uint4*)g_Wo16;
        uint4* wdst = (uint4*)(sm + K2_WO);
        for (int i = t2; i < 2176; i += 128) wdst[i] = wsrc[i];
        if (t2 < 128) { bs[t2] = b_out[t2]; g2s[t2] = g2[t2]; }
    }
    __syncthreads();

    // ---- GEMM ctx-apply: O[e][t] = sum_d ctxA[e][d] * p[t][d] ----
    {
        const int h = w >> 1, m0l = (w & 1) << 4;
        #pragma unroll
        for (int i = 0; i < 64; i++) acc[i] = 0.f;
        uint32_t aC = sb + K2_CTX + h * 2560u
                    + (uint32_t)(m0l + (lane & 15)) * 80 + ((lane >> 4) << 4);
        gemm_pass<2, 8>(acc, aC, b_lane_addr(sb, K2_BP + h * 64u, lane));
        // OB writes (QL dead after softmax; own rows exclusive) -- no barrier needed
        const int eg0 = (h << 5) + m0l + gp, eg1 = eg0 + 8;
        #pragma unroll
        for (int nt = 0; nt < 8; nt++) {
            #pragma unroll
            for (int s2 = 0; s2 < 2; s2++) {
                int cb = (nt << 4) + (s2 << 3) + tq;
                const float* a4 = acc + (nt << 3) + (s2 << 2);
                #pragma unroll
                for (int q = 0; q < 4; q++) {
                    int tcol = cb + (q & 1);
                    int eg = (q < 2) ? eg0 : eg1;
                    *(__half*)(sm + K2_OB + tcol * 272 + eg * 2) = __float2half_rn(a4[q]);
                }
            }
        }
    }
    __syncthreads();

    // ---- GEMM out: y[o][t] = sum_e Wo[o][e] * OB[t][e] ----
    #pragma unroll
    for (int i = 0; i < 64; i++) acc[i] = 0.f;
    gemm_pass<8, 8>(acc, a_lane_addr(sb, K2_WO, m0, 272, lane),
                    b_lane_addr(sb, K2_OB, lane));
    __syncthreads();   // OB reads done -> Ys overwrite
    {
        const int r0 = m0 + gp, r1 = r0 + 8;
        const float b0v = bs[r0], b1v = bs[r1];
        #pragma unroll
        for (int nt = 0; nt < 8; nt++) {
            #pragma unroll
            for (int s2 = 0; s2 < 2; s2++) {
                int cb = (nt << 4) + (s2 << 3) + tq;
                const float* a4 = acc + (nt << 3) + (s2 << 2);
                *(float2*)(Ys + r0 * 132 + cb) = make_float2(a4[0] + b0v, a4[1] + b0v);
                *(float2*)(Ys + r1 * 132 + cb) = make_float2(a4[2] + b1v, a4[3] + b1v);
            }
        }
    }
    __syncthreads();
    if (tid < 128) {
        float s = 0.f;
        #pragma unroll 16
        for (int o = 0; o < 128; o++) { float v = Ys[o * 132 + tid]; s = fmaf(v, v, s); }
        invs[tid] = SQRTC / fmaxf(sqrtf(s), 1e-12f);
    }
    __syncthreads();
    {
        const int to = tid & 127, oh = (tid >> 7) << 6;
        const float iv = invs[to];
        float* ob = out + (((size_t)b) << 21) + p0 + to;
        #pragma unroll 8
        for (int j = 0; j < 64; j++) {
            int o = oh + j;
            ob[(size_t)o << 14] = Ys[o * 132 + to] * iv * g2s[o];
        }
    }
}

// ---------------------------------------------------------------------------
extern "C" void kernel_launch(void* const* d_in, const int* in_sizes, int n_in,
                              void* d_out, int out_size) {
    const float* x    = (const float*)d_in[0];
    const float* g1   = (const float*)d_in[1];
    const float* wqkv = (const float*)d_in[2];
    const float* wout = (const float*)d_in[3];
    const float* bout = (const float*)d_in[4];
    const float* g2   = (const float*)d_in[5];
    float* out = (float*)d_out;

    cudaFuncSetAttribute(qkv_kernel, cudaFuncAttributeMaxDynamicSharedMemorySize, K1_SMEM);
    cudaFuncSetAttribute(out_kernel, cudaFuncAttributeMaxDynamicSharedMemorySize, K2_SMEM);

    prep_kernel<<<256, 256>>>(wqkv, g1, wout);
    dim3 grid(NN / 128, BB);
    qkv_kernel<<<grid, 256, K1_SMEM>>>(x);
    out_kernel<<<grid, 256, K2_SMEM>>>(x, bout, g2, out);
}

// round 6
// speedup vs baseline: 2.7837x; 1.4117x over previous
#include <cuda_runtime.h>
#include <cuda_fp16.h>
#include <cstdint>
#include <math.h>

#define BB 16
#define CC 128
#define NN 16384
#define SQRTC 11.313708498984761f
#define QSCALE 0.17677669529663688f

// ---- global scratch ----
__device__ __align__(16) __half g_W16[3][128 * 136];   // qkv weights fp16, padded rows
__device__ __align__(16) __half g_Wo16[128 * 136];     // out weights fp16
__device__ __align__(16) __half g_Xh[(size_t)2048 * 17408]; // forwarded X-hat operand tiles
__device__ float g_ctx[BB * 4 * 32 * 32];
__device__ float g_den[BB * CC];

// =============================== helpers ==================================
__device__ __forceinline__ uint32_t smem_u32(const void* p) {
    uint32_t a;
    asm("{ .reg .u64 t; cvta.to.shared.u64 t, %1; cvt.u32.u64 %0, t; }" : "=r"(a) : "l"(p));
    return a;
}
__device__ __forceinline__ void ldsm4(uint32_t addr, uint32_t& r0, uint32_t& r1,
                                      uint32_t& r2, uint32_t& r3) {
    asm volatile("ldmatrix.sync.aligned.m8n8.x4.shared.b16 {%0,%1,%2,%3}, [%4];"
                 : "=r"(r0), "=r"(r1), "=r"(r2), "=r"(r3) : "r"(addr));
}
__device__ __forceinline__ void mma8(float* c, uint32_t a0, uint32_t a1, uint32_t a2,
                                     uint32_t a3, uint32_t b0, uint32_t b1) {
    asm volatile(
        "mma.sync.aligned.m16n8k16.row.col.f32.f16.f16.f32 "
        "{%0,%1,%2,%3},{%4,%5,%6,%7},{%8,%9},{%0,%1,%2,%3};"
        : "+f"(c[0]), "+f"(c[1]), "+f"(c[2]), "+f"(c[3])
        : "r"(a0), "r"(a1), "r"(a2), "r"(a3), "r"(b0), "r"(b1));
}
// GEMM pass: A row-major [m][k], B stored [n][k] (stride 272B both)
template <int KSTEPS, int NT2>
__device__ __forceinline__ void gemm_pass(float* acc, uint32_t aLane, uint32_t bLane) {
    #pragma unroll
    for (int ks = 0; ks < KSTEPS; ks++) {
        uint32_t a0, a1, a2, a3;
        ldsm4(aLane + ks * 32, a0, a1, a2, a3);
        #pragma unroll
        for (int nt = 0; nt < NT2; nt++) {
            uint32_t b0, b1, b2, b3;
            ldsm4(bLane + nt * 4352 + ks * 32, b0, b1, b2, b3);
            mma8(acc + nt * 8,     a0, a1, a2, a3, b0, b1);
            mma8(acc + nt * 8 + 4, a0, a1, a2, a3, b2, b3);
        }
    }
}
__device__ __forceinline__ uint32_t a_lane_addr(uint32_t sb, uint32_t off, int m0,
                                                int rs, int lane) {
    return sb + off + (uint32_t)(m0 + (lane & 15)) * rs + ((lane >> 4) << 4);
}
__device__ __forceinline__ uint32_t b_lane_addr(uint32_t sb, uint32_t off, int lane) {
    return sb + off + (uint32_t)((lane & 7) + ((lane & 16) >> 1)) * 272 + ((lane & 8) << 1);
}

// =============================== prep ======================================
__global__ void prep_kernel(const float* __restrict__ wqkv, const float* __restrict__ g1,
                            const float* __restrict__ wout) {
    int i = blockIdx.x * 256 + threadIdx.x;   // 65536
    if (i < 49152) {
        int g = i >> 14, r = i & 16383, o = r >> 7, c = r & 127;
        float v = wqkv[((g << 7) + o) * CC + c] * g1[c] * SQRTC;
        g_W16[g][o * 136 + c] = __float2half_rn(v);
    } else {
        int j = i - 49152;
        int o = j >> 7, e = j & 127;
        g_Wo16[o * 136 + e] = __float2half_rn(wout[(o << 7) + e]);
    }
    if (i < BB * 4096) g_ctx[i] = 0.f;
    if (i < BB * CC)   g_den[i] = 0.f;
}

// =============================== K1 =======================================
// regions: Wk@0 | Wv@34816 | X@69632 | Xs fp32 @104448 (E/V overlay) | inv @174080
#define K1_WK   0u
#define K1_WV   34816u
#define K1_X    69632u
#define K1_XS   104448u
#define K1_E    104448u
#define K1_V    139264u
#define K1_INV  174080u
#define K1_SMEM 174592

__global__ __launch_bounds__(512, 1) void qkv_kernel(const float* __restrict__ x) {
    extern __shared__ char sm[];
    const uint32_t sb = smem_u32(sm);
    const int tid = threadIdx.x, lane = tid & 31, w = tid >> 5;
    const int b = blockIdx.y, bx = blockIdx.x, p0 = bx << 7;
    float* Xs  = (float*)(sm + K1_XS);
    float* inv = (float*)(sm + K1_INV);

    // phase 0: load x tile + Wk&Wv (contiguous)
    {
        float4* Xs4 = (float4*)Xs;
        const float* xb = x + (((size_t)b) << 21) + p0;
        for (int i = tid; i < 4096; i += 512) {
            int c = i >> 5, t4 = i & 31;
            Xs4[i] = *((const float4*)(xb + ((size_t)c << 14)) + t4);
        }
        const uint4* wsrc = (const uint4*)g_W16[1];
        uint4* wdst = (uint4*)(sm + K1_WK);
        for (int i = tid; i < 4352; i += 512) wdst[i] = wsrc[i];
    }
    __syncthreads();
    // rmsnorm reduce: 2 threads per token
    if (tid < 256) {
        const int t = tid >> 1, half = tid & 1;
        float s = 0.f;
        #pragma unroll 16
        for (int j = 0; j < 64; j++) {
            float v = Xs[(((half << 6) + j) << 7) + t];
            s = fmaf(v, v, s);
        }
        s += __shfl_xor_sync(0xffffffffu, s, 1);
        if (half == 0) inv[t] = 1.0f / fmaxf(sqrtf(s), 1e-12f);
    }
    __syncthreads();
    // pack X operand [t][c] fp16 (inv folded): 4 threads per token
    {
        const int t = tid >> 2, c0 = (tid & 3) << 5;
        const float it = inv[t];
        char* px = sm + K1_X + t * 272;
        #pragma unroll 8
        for (int j = 0; j < 16; j++) {
            int c = c0 + (j << 1);
            __half2 h = __floats2half2_rn(Xs[(c << 7) + t] * it, Xs[((c + 1) << 7) + t] * it);
            *(uint32_t*)(px + c * 2) = *(uint32_t*)&h;
        }
    }
    __syncthreads();
    // export X-hat operand to gmem for K2
    {
        const uint4* s4 = (const uint4*)(sm + K1_X);
        uint4* g4 = (uint4*)g_Xh + (size_t)((b << 7) + bx) * 2176;
        for (int i = tid; i < 2176; i += 512) g4[i] = s4[i];
    }

    const int m0 = (w & 7) << 4, th = w >> 3;
    const int gp = lane >> 2, tq = (lane & 3) << 1;
    const uint32_t bX = b_lane_addr(sb, K1_X + th * 17408u, lane);

    // ---- GEMM k ----
    float acc[32];
    #pragma unroll
    for (int i = 0; i < 32; i++) acc[i] = 0.f;
    gemm_pass<8, 4>(acc, a_lane_addr(sb, K1_WK, m0, 272, lane), bX);

    // epilogue k: exp -> E, den atomics (Xs dead -> E overlay safe)
    {
        const int r0 = m0 + gp, r1 = r0 + 8;
        float d0 = 0.f, d1 = 0.f;
        #pragma unroll
        for (int nt = 0; nt < 4; nt++) {
            #pragma unroll
            for (int s2 = 0; s2 < 2; s2++) {
                int cb = (th << 6) + (nt << 4) + (s2 << 3) + tq;
                const float* a4 = acc + (nt << 3) + (s2 << 2);
                float e00 = __expf(a4[0]), e01 = __expf(a4[1]);
                float e10 = __expf(a4[2]), e11 = __expf(a4[3]);
                d0 += e00 + e01; d1 += e10 + e11;
                __half2 h0 = __floats2half2_rn(e00, e01);
                __half2 h1 = __floats2half2_rn(e10, e11);
                *(uint32_t*)(sm + K1_E + r0 * 272 + cb * 2) = *(uint32_t*)&h0;
                *(uint32_t*)(sm + K1_E + r1 * 272 + cb * 2) = *(uint32_t*)&h1;
            }
        }
        d0 += __shfl_xor_sync(0xffffffffu, d0, 1);
        d0 += __shfl_xor_sync(0xffffffffu, d0, 2);
        d1 += __shfl_xor_sync(0xffffffffu, d1, 1);
        d1 += __shfl_xor_sync(0xffffffffu, d1, 2);
        if ((lane & 3) == 0) {
            atomicAdd(&g_den[(b << 7) + r0], d0);
            atomicAdd(&g_den[(b << 7) + r1], d1);
        }
    }

    // ---- GEMM v ----
    #pragma unroll
    for (int i = 0; i < 32; i++) acc[i] = 0.f;
    gemm_pass<8, 4>(acc, a_lane_addr(sb, K1_WV, m0, 272, lane), bX);
    {
        const int r0 = m0 + gp, r1 = r0 + 8;
        #pragma unroll
        for (int nt = 0; nt < 4; nt++) {
            #pragma unroll
            for (int s2 = 0; s2 < 2; s2++) {
                int cb = (th << 6) + (nt << 4) + (s2 << 3) + tq;
                const float* a4 = acc + (nt << 3) + (s2 << 2);
                __half2 h0 = __floats2half2_rn(a4[0], a4[1]);
                __half2 h1 = __floats2half2_rn(a4[2], a4[3]);
                *(uint32_t*)(sm + K1_V + r0 * 272 + cb * 2) = *(uint32_t*)&h0;
                *(uint32_t*)(sm + K1_V + r1 * 272 + cb * 2) = *(uint32_t*)&h1;
            }
        }
    }
    __syncthreads();

    // ---- gram: ctx[d][e] += sum_t E[d][t] * V[e][t]; warps split token ksteps ----
    {
        const int h = (w & 7) >> 1;
        float acc16[16];
        #pragma unroll
        for (int i = 0; i < 16; i++) acc16[i] = 0.f;
        uint32_t aE = a_lane_addr(sb, K1_E, m0, 272, lane) + th * 128u;
        uint32_t bV = b_lane_addr(sb, K1_V + h * 8704u, lane) + th * 128u;
        gemm_pass<4, 2>(acc16, aE, bV);

        const int dl0 = (m0 + gp) & 31, dl1 = dl0 + 8;
        float* cbase = g_ctx + (((b << 2) + h) << 10);
        #pragma unroll
        for (int nt = 0; nt < 2; nt++) {
            #pragma unroll
            for (int s2 = 0; s2 < 2; s2++) {
                int cb = (nt << 4) + (s2 << 3) + tq;
                const float* a4 = acc16 + (nt << 3) + (s2 << 2);
                atomicAdd(cbase + (dl0 << 5) + cb,     a4[0]);
                atomicAdd(cbase + (dl0 << 5) + cb + 1, a4[1]);
                atomicAdd(cbase + (dl1 << 5) + cb,     a4[2]);
                atomicAdd(cbase + (dl1 << 5) + cb + 1, a4[3]);
            }
        }
    }
}

// =============================== K2 =======================================
// regions: Wq@0 (Bp overlay) | X@34816 | QL@69632 fp32 s132 (OB/Ys overlay)
//          ctxA@137216 | Wo@147456 | bias@182272 | g2@182784 | invs@183296
#define K2_WQ   0u
#define K2_BP   0u
#define K2_X    34816u
#define K2_QL   69632u
#define K2_OB   69632u
#define K2_YS   69632u
#define K2_CTX  137216u
#define K2_WO   147456u
#define K2_BIAS 182272u
#define K2_G2   182784u
#define K2_INVS 183296u
#define K2_SMEM 183808

__global__ __launch_bounds__(512, 1) void out_kernel(const float* __restrict__ b_out,
                                                     const float* __restrict__ g2,
                                                     float* __restrict__ out) {
    extern __shared__ char sm[];
    const uint32_t sb = smem_u32(sm);
    const int tid = threadIdx.x, lane = tid & 31, w = tid >> 5;
    const int b = blockIdx.y, bx = blockIdx.x, p0 = bx << 7;
    float* QL   = (float*)(sm + K2_QL);      // stride 132
    float* Ys   = (float*)(sm + K2_YS);      // stride 132
    float* invs = (float*)(sm + K2_INVS);
    float* bs   = (float*)(sm + K2_BIAS);
    float* g2s  = (float*)(sm + K2_G2);

    // phase 0: all loads (X-hat, Wq, Wo, ctxA, bias, g2)
    {
        const uint4* xsrc = (const uint4*)g_Xh + (size_t)((b << 7) + bx) * 2176;
        uint4* xdst = (uint4*)(sm + K2_X);
        for (int i = tid; i < 2176; i += 512) xdst[i] = xsrc[i];
        const uint4* wsrc = (const uint4*)g_W16[0];
        uint4* wdst = (uint4*)(sm + K2_WQ);
        for (int i = tid; i < 2176; i += 512) wdst[i] = wsrc[i];
        const uint4* osrc = (const uint4*)g_Wo16;
        uint4* odst = (uint4*)(sm + K2_WO);
        for (int i = tid; i < 2176; i += 512) odst[i] = osrc[i];
        // ctxA[h][e][d] = ctx[d][e]/den (e-row stride 80B)
        #pragma unroll
        for (int j = 0; j < 8; j++) {
            int v = tid + (j << 9);
            int h = v >> 10, e = (v >> 5) & 31, d = v & 31;
            float c = g_ctx[(((b << 2) + h) << 10) + (d << 5) + e]
                    / g_den[(b << 7) + (h << 5) + d];
            *(__half*)(sm + K2_CTX + h * 2560 + e * 80 + d * 2) = __float2half_rn(c);
        }
        if (tid < 128) { bs[tid] = b_out[tid]; g2s[tid] = g2[tid]; }
    }
    __syncthreads();

    const int m0 = (w & 7) << 4, th = w >> 3;
    const int gp = lane >> 2, tq = (lane & 3) << 1;

    // ---- GEMM q ----
    float acc[32];
    #pragma unroll
    for (int i = 0; i < 32; i++) acc[i] = 0.f;
    gemm_pass<8, 4>(acc, a_lane_addr(sb, K2_WQ, m0, 272, lane),
                    b_lane_addr(sb, K2_X + th * 17408u, lane));
    {
        const int r0 = m0 + gp, r1 = r0 + 8;
        #pragma unroll
        for (int nt = 0; nt < 4; nt++) {
            #pragma unroll
            for (int s2 = 0; s2 < 2; s2++) {
                int cb = (th << 6) + (nt << 4) + (s2 << 3) + tq;
                const float* a4 = acc + (nt << 3) + (s2 << 2);
                *(float2*)(QL + r0 * 132 + cb) = make_float2(a4[0], a4[1]);
                *(float2*)(QL + r1 * 132 + cb) = make_float2(a4[2], a4[3]);
            }
        }
    }
    __syncthreads();

    // ---- softmax: one (token, head) per thread -> Bp (over Wq, dead) ----
    {
        const int t = tid & 127, h = tid >> 7;
        char* pb = sm + K2_BP + t * 272 + (h << 6);
        float pv[32];
        float m = -1e30f;
        #pragma unroll 8
        for (int d = 0; d < 32; d++) {
            pv[d] = QL[((h << 5) + d) * 132 + t];
            m = fmaxf(m, pv[d]);
        }
        float s = 0.f;
        #pragma unroll 8
        for (int d = 0; d < 32; d++) { pv[d] = __expf(pv[d] - m); s += pv[d]; }
        float rcp = QSCALE / s;
        #pragma unroll 8
        for (int d2 = 0; d2 < 16; d2++) {
            __half2 hh = __floats2half2_rn(pv[d2 << 1] * rcp, pv[(d2 << 1) + 1] * rcp);
            *(uint32_t*)(pb + (d2 << 2)) = *(uint32_t*)&hh;
        }
    }
    __syncthreads();

    // ---- GEMM ctx-apply: O[e][t] = sum_d ctxA[e][d] * p[t][d] ----
    {
        const int h = (w & 7) >> 1, m0l = (w & 1) << 4;
        #pragma unroll
        for (int i = 0; i < 32; i++) acc[i] = 0.f;
        uint32_t aC = sb + K2_CTX + h * 2560u
                    + (uint32_t)(m0l + (lane & 15)) * 80 + ((lane >> 4) << 4);
        gemm_pass<2, 4>(acc, aC, b_lane_addr(sb, K2_BP + (h << 6) + th * 17408u, lane));
        // OB writes over QL (dead after softmax)
        const int eg0 = (h << 5) + m0l + gp, eg1 = eg0 + 8;
        #pragma unroll
        for (int nt = 0; nt < 4; nt++) {
            #pragma unroll
            for (int s2 = 0; s2 < 2; s2++) {
                int cb = (th << 6) + (nt << 4) + (s2 << 3) + tq;
                const float* a4 = acc + (nt << 3) + (s2 << 2);
                #pragma unroll
                for (int q = 0; q < 4; q++) {
                    int tcol = cb + (q & 1);
                    int eg = (q < 2) ? eg0 : eg1;
                    *(__half*)(sm + K2_OB + tcol * 272 + eg * 2) = __float2half_rn(a4[q]);
                }
            }
        }
    }
    __syncthreads();

    // ---- GEMM out: y[o][t] = sum_e Wo[o][e] * OB[t][e] ----
    #pragma unroll
    for (int i = 0; i < 32; i++) acc[i] = 0.f;
    gemm_pass<8, 4>(acc, a_lane_addr(sb, K2_WO, m0, 272, lane),
                    b_lane_addr(sb, K2_OB + th * 17408u, lane));
    __syncthreads();   // OB reads done -> Ys overwrite
    {
        const int r0 = m0 + gp, r1 = r0 + 8;
        const float b0v = bs[r0], b1v = bs[r1];
        #pragma unroll
        for (int nt = 0; nt < 4; nt++) {
            #pragma unroll
            for (int s2 = 0; s2 < 2; s2++) {
                int cb = (th << 6) + (nt << 4) + (s2 << 3) + tq;
                const float* a4 = acc + (nt << 3) + (s2 << 2);
                *(float2*)(Ys + r0 * 132 + cb) = make_float2(a4[0] + b0v, a4[1] + b0v);
                *(float2*)(Ys + r1 * 132 + cb) = make_float2(a4[2] + b1v, a4[3] + b1v);
            }
        }
    }
    __syncthreads();
    // rmsnorm reduce: 4 threads per token
    {
        const int t = tid >> 2, q4 = tid & 3;
        float s = 0.f;
        #pragma unroll 8
        for (int j = 0; j < 32; j++) {
            float v = Ys[((q4 << 5) + j) * 132 + t];
            s = fmaf(v, v, s);
        }
        s += __shfl_xor_sync(0xffffffffu, s, 1);
        s += __shfl_xor_sync(0xffffffffu, s, 2);
        if (q4 == 0) invs[t] = SQRTC / fmaxf(sqrtf(s), 1e-12f);
    }
    __syncthreads();
    {
        const int to = tid & 127, oh = (tid >> 7) << 5;
        const float iv = invs[to];
        float* ob = out + (((size_t)b) << 21) + p0 + to;
        #pragma unroll 8
        for (int j = 0; j < 32; j++) {
            int o = oh + j;
            ob[(size_t)o << 14] = Ys[o * 132 + to] * iv * g2s[o];
        }
    }
}

// ---------------------------------------------------------------------------
extern "C" void kernel_launch(void* const* d_in, const int* in_sizes, int n_in,
                              void* d_out, int out_size) {
    const float* x    = (const float*)d_in[0];
    const float* g1   = (const float*)d_in[1];
    const float* wqkv = (const float*)d_in[2];
    const float* wout = (const float*)d_in[3];
    const float* bout = (const float*)d_in[4];
    const float* g2   = (const float*)d_in[5];
    float* out = (float*)d_out;

    cudaFuncSetAttribute(qkv_kernel, cudaFuncAttributeMaxDynamicSharedMemorySize, K1_SMEM);
    cudaFuncSetAttribute(out_kernel, cudaFuncAttributeMaxDynamicSharedMemorySize, K2_SMEM);

    prep_kernel<<<256, 256>>>(wqkv, g1, wout);
    dim3 grid(NN / 128, BB);
    qkv_kernel<<<grid, 512, K1_SMEM>>>(x);
    out_kernel<<<grid, 512, K2_SMEM>>>(bout, g2, out);
}

// round 7
// speedup vs baseline: 2.9345x; 1.0542x over previous
#include <cuda_runtime.h>
#include <cuda_fp16.h>
#include <cstdint>
#include <math.h>

#define BB 16
#define CC 128
#define NN 16384
#define SQRTC 11.313708498984761f
#define QSCALE 0.17677669529663688f
#define L2E 1.4426950408889634f

// ---- global scratch ----
__device__ __align__(16) __half g_W16[3][128 * 136];   // qkv weights fp16, padded rows
__device__ __align__(16) __half g_Wo16[128 * 136];     // out weights fp16
__device__ __align__(16) __half g_Xh[(size_t)2048 * 17408]; // forwarded X-hat operand tiles
__device__ float g_ctx[BB * 4 * 32 * 32];
__device__ float g_den[BB * CC];

// =============================== helpers ==================================
__device__ __forceinline__ uint32_t smem_u32(const void* p) {
    uint32_t a;
    asm("{ .reg .u64 t; cvta.to.shared.u64 t, %1; cvt.u32.u64 %0, t; }" : "=r"(a) : "l"(p));
    return a;
}
__device__ __forceinline__ void ldsm4(uint32_t addr, uint32_t& r0, uint32_t& r1,
                                      uint32_t& r2, uint32_t& r3) {
    asm volatile("ldmatrix.sync.aligned.m8n8.x4.shared.b16 {%0,%1,%2,%3}, [%4];"
                 : "=r"(r0), "=r"(r1), "=r"(r2), "=r"(r3) : "r"(addr));
}
__device__ __forceinline__ void mma8(float* c, uint32_t a0, uint32_t a1, uint32_t a2,
                                     uint32_t a3, uint32_t b0, uint32_t b1) {
    asm volatile(
        "mma.sync.aligned.m16n8k16.row.col.f32.f16.f16.f32 "
        "{%0,%1,%2,%3},{%4,%5,%6,%7},{%8,%9},{%0,%1,%2,%3};"
        : "+f"(c[0]), "+f"(c[1]), "+f"(c[2]), "+f"(c[3])
        : "r"(a0), "r"(a1), "r"(a2), "r"(a3), "r"(b0), "r"(b1));
}
// two fp16 exponentials in one MUFU op: e = exp(v) for v pre-scaled by log2(e)
__device__ __forceinline__ uint32_t exp2_h2(float v0, float v1) {
    __half2 l = __floats2half2_rn(v0, v1);
    uint32_t e;
    asm("ex2.approx.f16x2 %0, %1;" : "=r"(e) : "r"(*(uint32_t*)&l));
    return e;
}
// GEMM pass: A row-major [m][k], B stored [n][k] (stride 272B both)
template <int KSTEPS, int NT2>
__device__ __forceinline__ void gemm_pass(float* acc, uint32_t aLane, uint32_t bLane) {
    #pragma unroll
    for (int ks = 0; ks < KSTEPS; ks++) {
        uint32_t a0, a1, a2, a3;
        ldsm4(aLane + ks * 32, a0, a1, a2, a3);
        #pragma unroll
        for (int nt = 0; nt < NT2; nt++) {
            uint32_t b0, b1, b2, b3;
            ldsm4(bLane + nt * 4352 + ks * 32, b0, b1, b2, b3);
            mma8(acc + nt * 8,     a0, a1, a2, a3, b0, b1);
            mma8(acc + nt * 8 + 4, a0, a1, a2, a3, b2, b3);
        }
    }
}
__device__ __forceinline__ uint32_t a_lane_addr(uint32_t sb, uint32_t off, int m0,
                                                int rs, int lane) {
    return sb + off + (uint32_t)(m0 + (lane & 15)) * rs + ((lane >> 4) << 4);
}
__device__ __forceinline__ uint32_t b_lane_addr(uint32_t sb, uint32_t off, int lane) {
    return sb + off + (uint32_t)((lane & 7) + ((lane & 16) >> 1)) * 272 + ((lane & 8) << 1);
}

// =============================== prep ======================================
__global__ void prep_kernel(const float* __restrict__ wqkv, const float* __restrict__ g1,
                            const float* __restrict__ wout) {
    int i = blockIdx.x * 256 + threadIdx.x;   // 65536
    if (i < 49152) {
        int g = i >> 14, r = i & 16383, o = r >> 7, c = r & 127;
        float v = wqkv[((g << 7) + o) * CC + c] * g1[c] * SQRTC;
        g_W16[g][o * 136 + c] = __float2half_rn(v);
    } else {
        int j = i - 49152;
        int o = j >> 7, e = j & 127;
        g_Wo16[o * 136 + e] = __float2half_rn(wout[(o << 7) + e]);
    }
    if (i < BB * 4096) g_ctx[i] = 0.f;
    if (i < BB * CC)   g_den[i] = 0.f;
}

// =============================== K1 =======================================
// regions: Wk@0 | Wv@34816 | X@69632 | Xs fp32 @104448 (E/V overlay) | inv @174080
#define K1_WK   0u
#define K1_WV   34816u
#define K1_X    69632u
#define K1_XS   104448u
#define K1_E    104448u
#define K1_V    139264u
#define K1_INV  174080u
#define K1_SMEM 174592

__global__ __launch_bounds__(512, 1) void qkv_kernel(const float* __restrict__ x) {
    extern __shared__ char sm[];
    const uint32_t sb = smem_u32(sm);
    const int tid = threadIdx.x, lane = tid & 31, w = tid >> 5;
    const int b = blockIdx.y, bx = blockIdx.x, p0 = bx << 7;
    float* Xs  = (float*)(sm + K1_XS);
    float* inv = (float*)(sm + K1_INV);

    // phase 0: load x tile + Wk&Wv (contiguous)
    {
        float4* Xs4 = (float4*)Xs;
        const float* xb = x + (((size_t)b) << 21) + p0;
        for (int i = tid; i < 4096; i += 512) {
            int c = i >> 5, t4 = i & 31;
            Xs4[i] = *((const float4*)(xb + ((size_t)c << 14)) + t4);
        }
        const uint4* wsrc = (const uint4*)g_W16[1];
        uint4* wdst = (uint4*)(sm + K1_WK);
        for (int i = tid; i < 4352; i += 512) wdst[i] = wsrc[i];
    }
    __syncthreads();
    // rmsnorm reduce: 2 threads per token
    if (tid < 256) {
        const int t = tid >> 1, half = tid & 1;
        float s = 0.f;
        #pragma unroll 16
        for (int j = 0; j < 64; j++) {
            float v = Xs[(((half << 6) + j) << 7) + t];
            s = fmaf(v, v, s);
        }
        s += __shfl_xor_sync(0xffffffffu, s, 1);
        if (half == 0) inv[t] = 1.0f / fmaxf(sqrtf(s), 1e-12f);
    }
    __syncthreads();
    // pack X operand [t][c] fp16 (inv folded): 4 threads per token
    {
        const int t = tid >> 2, c0 = (tid & 3) << 5;
        const float it = inv[t];
        char* px = sm + K1_X + t * 272;
        #pragma unroll 8
        for (int j = 0; j < 16; j++) {
            int c = c0 + (j << 1);
            __half2 h = __floats2half2_rn(Xs[(c << 7) + t] * it, Xs[((c + 1) << 7) + t] * it);
            *(uint32_t*)(px + c * 2) = *(uint32_t*)&h;
        }
    }
    __syncthreads();
    // export X-hat operand to gmem for K2
    {
        const uint4* s4 = (const uint4*)(sm + K1_X);
        uint4* g4 = (uint4*)g_Xh + (size_t)((b << 7) + bx) * 2176;
        for (int i = tid; i < 2176; i += 512) g4[i] = s4[i];
    }

    const int m0 = (w & 7) << 4, th = w >> 3;
    const int gp = lane >> 2, tq = (lane & 3) << 1;
    const uint32_t bX = b_lane_addr(sb, K1_X + th * 17408u, lane);

    // ---- GEMM k ----
    float acc[32];
    #pragma unroll
    for (int i = 0; i < 32; i++) acc[i] = 0.f;
    gemm_pass<8, 4>(acc, a_lane_addr(sb, K1_WK, m0, 272, lane), bX);

    // epilogue k: exp via ex2.f16x2 -> E, den atomics (Xs dead -> E overlay safe)
    {
        const int r0 = m0 + gp, r1 = r0 + 8;
        float d0 = 0.f, d1 = 0.f;
        #pragma unroll
        for (int nt = 0; nt < 4; nt++) {
            #pragma unroll
            for (int s2 = 0; s2 < 2; s2++) {
                int cb = (th << 6) + (nt << 4) + (s2 << 3) + tq;
                const float* a4 = acc + (nt << 3) + (s2 << 2);
                uint32_t e0 = exp2_h2(a4[0] * L2E, a4[1] * L2E);
                uint32_t e1 = exp2_h2(a4[2] * L2E, a4[3] * L2E);
                *(uint32_t*)(sm + K1_E + r0 * 272 + cb * 2) = e0;
                *(uint32_t*)(sm + K1_E + r1 * 272 + cb * 2) = e1;
                float2 f0 = __half22float2(*(__half2*)&e0);
                float2 f1 = __half22float2(*(__half2*)&e1);
                d0 += f0.x + f0.y;
                d1 += f1.x + f1.y;
            }
        }
        d0 += __shfl_xor_sync(0xffffffffu, d0, 1);
        d0 += __shfl_xor_sync(0xffffffffu, d0, 2);
        d1 += __shfl_xor_sync(0xffffffffu, d1, 1);
        d1 += __shfl_xor_sync(0xffffffffu, d1, 2);
        if ((lane & 3) == 0) {
            atomicAdd(&g_den[(b << 7) + r0], d0);
            atomicAdd(&g_den[(b << 7) + r1], d1);
        }
    }

    // ---- GEMM v ----
    #pragma unroll
    for (int i = 0; i < 32; i++) acc[i] = 0.f;
    gemm_pass<8, 4>(acc, a_lane_addr(sb, K1_WV, m0, 272, lane), bX);
    {
        const int r0 = m0 + gp, r1 = r0 + 8;
        #pragma unroll
        for (int nt = 0; nt < 4; nt++) {
            #pragma unroll
            for (int s2 = 0; s2 < 2; s2++) {
                int cb = (th << 6) + (nt << 4) + (s2 << 3) + tq;
                const float* a4 = acc + (nt << 3) + (s2 << 2);
                __half2 h0 = __floats2half2_rn(a4[0], a4[1]);
                __half2 h1 = __floats2half2_rn(a4[2], a4[3]);
                *(uint32_t*)(sm + K1_V + r0 * 272 + cb * 2) = *(uint32_t*)&h0;
                *(uint32_t*)(sm + K1_V + r1 * 272 + cb * 2) = *(uint32_t*)&h1;
            }
        }
    }
    __syncthreads();

    // ---- gram: ctx[d][e] += sum_t E[d][t] * V[e][t]; warps split token ksteps ----
    {
        const int h = (w & 7) >> 1;
        float acc16[16];
        #pragma unroll
        for (int i = 0; i < 16; i++) acc16[i] = 0.f;
        uint32_t aE = a_lane_addr(sb, K1_E, m0, 272, lane) + th * 128u;
        uint32_t bV = b_lane_addr(sb, K1_V + h * 8704u, lane) + th * 128u;
        gemm_pass<4, 2>(acc16, aE, bV);

        const int dl0 = (m0 + gp) & 31, dl1 = dl0 + 8;
        float* cbase = g_ctx + (((b << 2) + h) << 10);
        #pragma unroll
        for (int nt = 0; nt < 2; nt++) {
            #pragma unroll
            for (int s2 = 0; s2 < 2; s2++) {
                int cb = (nt << 4) + (s2 << 3) + tq;
                const float* a4 = acc16 + (nt << 3) + (s2 << 2);
                atomicAdd(cbase + (dl0 << 5) + cb,     a4[0]);
                atomicAdd(cbase + (dl0 << 5) + cb + 1, a4[1]);
                atomicAdd(cbase + (dl1 << 5) + cb,     a4[2]);
                atomicAdd(cbase + (dl1 << 5) + cb + 1, a4[3]);
            }
        }
    }
}

// =============================== K2 =======================================
// regions: Wq@0 (Bp overlay) | X@34816 | QL@69632 fp32 s132 (OB/Ys overlay)
//          ctxA@137216 | Wo@147456 | bias@182272 | g2@182784 | invs@183296
#define K2_WQ   0u
#define K2_BP   0u
#define K2_X    34816u
#define K2_QL   69632u
#define K2_OB   69632u
#define K2_YS   69632u
#define K2_CTX  137216u
#define K2_WO   147456u
#define K2_BIAS 182272u
#define K2_G2   182784u
#define K2_INVS 183296u
#define K2_SMEM 183808

__global__ __launch_bounds__(512, 1) void out_kernel(const float* __restrict__ b_out,
                                                     const float* __restrict__ g2,
                                                     float* __restrict__ out) {
    extern __shared__ char sm[];
    const uint32_t sb = smem_u32(sm);
    const int tid = threadIdx.x, lane = tid & 31, w = tid >> 5;
    const int b = blockIdx.y, bx = blockIdx.x, p0 = bx << 7;
    float* QL   = (float*)(sm + K2_QL);      // stride 132
    float* Ys   = (float*)(sm + K2_YS);      // stride 132
    float* invs = (float*)(sm + K2_INVS);
    float* bs   = (float*)(sm + K2_BIAS);
    float* g2s  = (float*)(sm + K2_G2);

    // phase 0: all loads (X-hat, Wq, Wo, ctxA, bias, g2)
    {
        const uint4* xsrc = (const uint4*)g_Xh + (size_t)((b << 7) + bx) * 2176;
        uint4* xdst = (uint4*)(sm + K2_X);
        for (int i = tid; i < 2176; i += 512) xdst[i] = xsrc[i];
        const uint4* wsrc = (const uint4*)g_W16[0];
        uint4* wdst = (uint4*)(sm + K2_WQ);
        for (int i = tid; i < 2176; i += 512) wdst[i] = wsrc[i];
        const uint4* osrc = (const uint4*)g_Wo16;
        uint4* odst = (uint4*)(sm + K2_WO);
        for (int i = tid; i < 2176; i += 512) odst[i] = osrc[i];
        // ctxA[h][e][d] = ctx[d][e]/den (e-row stride 80B)
        #pragma unroll
        for (int j = 0; j < 8; j++) {
            int v = tid + (j << 9);
            int h = v >> 10, e = (v >> 5) & 31, d = v & 31;
            float c = g_ctx[(((b << 2) + h) << 10) + (d << 5) + e]
                    / g_den[(b << 7) + (h << 5) + d];
            *(__half*)(sm + K2_CTX + h * 2560 + e * 80 + d * 2) = __float2half_rn(c);
        }
        if (tid < 128) { bs[tid] = b_out[tid]; g2s[tid] = g2[tid]; }
    }
    __syncthreads();

    const int m0 = (w & 7) << 4, th = w >> 3;
    const int gp = lane >> 2, tq = (lane & 3) << 1;

    // ---- GEMM q ----
    float acc[32];
    #pragma unroll
    for (int i = 0; i < 32; i++) acc[i] = 0.f;
    gemm_pass<8, 4>(acc, a_lane_addr(sb, K2_WQ, m0, 272, lane),
                    b_lane_addr(sb, K2_X + th * 17408u, lane));
    {
        const int r0 = m0 + gp, r1 = r0 + 8;
        #pragma unroll
        for (int nt = 0; nt < 4; nt++) {
            #pragma unroll
            for (int s2 = 0; s2 < 2; s2++) {
                int cb = (th << 6) + (nt << 4) + (s2 << 3) + tq;
                const float* a4 = acc + (nt << 3) + (s2 << 2);
                *(float2*)(QL + r0 * 132 + cb) = make_float2(a4[0], a4[1]);
                *(float2*)(QL + r1 * 132 + cb) = make_float2(a4[2], a4[3]);
            }
        }
    }
    __syncthreads();

    // ---- softmax via ex2.f16x2: one (token, head) per thread -> Bp ----
    {
        const int t = tid & 127, h = tid >> 7;
        char* pb = sm + K2_BP + t * 272 + (h << 6);
        float pv[32];
        float m = -1e30f;
        #pragma unroll 8
        for (int d = 0; d < 32; d++) {
            pv[d] = QL[((h << 5) + d) * 132 + t];
            m = fmaxf(m, pv[d]);
        }
        uint32_t eh[16];
        float s = 0.f;
        #pragma unroll
        for (int d2 = 0; d2 < 16; d2++) {
            eh[d2] = exp2_h2((pv[d2 << 1] - m) * L2E, (pv[(d2 << 1) + 1] - m) * L2E);
            float2 f = __half22float2(*(__half2*)&eh[d2]);
            s += f.x + f.y;
        }
        __half2 r2 = __float2half2_rn(QSCALE / s);
        #pragma unroll
        for (int d2 = 0; d2 < 16; d2++) {
            __half2 p2 = __hmul2(*(__half2*)&eh[d2], r2);
            *(uint32_t*)(pb + (d2 << 2)) = *(uint32_t*)&p2;
        }
    }
    __syncthreads();

    // ---- GEMM ctx-apply: O[e][t] = sum_d ctxA[e][d] * p[t][d] ----
    {
        const int h = (w & 7) >> 1, m0l = (w & 1) << 4;
        #pragma unroll
        for (int i = 0; i < 32; i++) acc[i] = 0.f;
        uint32_t aC = sb + K2_CTX + h * 2560u
                    + (uint32_t)(m0l + (lane & 15)) * 80 + ((lane >> 4) << 4);
        gemm_pass<2, 4>(acc, aC, b_lane_addr(sb, K2_BP + (h << 6) + th * 17408u, lane));
        // OB writes over QL (dead after softmax)
        const int eg0 = (h << 5) + m0l + gp, eg1 = eg0 + 8;
        #pragma unroll
        for (int nt = 0; nt < 4; nt++) {
            #pragma unroll
            for (int s2 = 0; s2 < 2; s2++) {
                int cb = (th << 6) + (nt << 4) + (s2 << 3) + tq;
                const float* a4 = acc + (nt << 3) + (s2 << 2);
                #pragma unroll
                for (int q = 0; q < 4; q++) {
                    int tcol = cb + (q & 1);
                    int eg = (q < 2) ? eg0 : eg1;
                    *(__half*)(sm + K2_OB + tcol * 272 + eg * 2) = __float2half_rn(a4[q]);
                }
            }
        }
    }
    __syncthreads();

    // ---- GEMM out: y[o][t] = sum_e Wo[o][e] * OB[t][e] ----
    #pragma unroll
    for (int i = 0; i < 32; i++) acc[i] = 0.f;
    gemm_pass<8, 4>(acc, a_lane_addr(sb, K2_WO, m0, 272, lane),
                    b_lane_addr(sb, K2_OB + th * 17408u, lane));
    __syncthreads();   // OB reads done -> Ys overwrite
    {
        const int r0 = m0 + gp, r1 = r0 + 8;
        const float b0v = bs[r0], b1v = bs[r1];
        #pragma unroll
        for (int nt = 0; nt < 4; nt++) {
            #pragma unroll
            for (int s2 = 0; s2 < 2; s2++) {
                int cb = (th << 6) + (nt << 4) + (s2 << 3) + tq;
                const float* a4 = acc + (nt << 3) + (s2 << 2);
                *(float2*)(Ys + r0 * 132 + cb) = make_float2(a4[0] + b0v, a4[1] + b0v);
                *(float2*)(Ys + r1 * 132 + cb) = make_float2(a4[2] + b1v, a4[3] + b1v);
            }
        }
    }
    __syncthreads();
    // rmsnorm reduce: 4 threads per token
    {
        const int t = tid >> 2, q4 = tid & 3;
        float s = 0.f;
        #pragma unroll 8
        for (int j = 0; j < 32; j++) {
            float v = Ys[((q4 << 5) + j) * 132 + t];
            s = fmaf(v, v, s);
        }
        s += __shfl_xor_sync(0xffffffffu, s, 1);
        s += __shfl_xor_sync(0xffffffffu, s, 2);
        if (q4 == 0) invs[t] = SQRTC / fmaxf(sqrtf(s), 1e-12f);
    }
    __syncthreads();
    {
        const int to = tid & 127, oh = (tid >> 7) << 5;
        const float iv = invs[to];
        float* ob = out + (((size_t)b) << 21) + p0 + to;
        #pragma unroll 8
        for (int j = 0; j < 32; j++) {
            int o = oh + j;
            ob[(size_t)o << 14] = Ys[o * 132 + to] * iv * g2s[o];
        }
    }
}

// ---------------------------------------------------------------------------
extern "C" void kernel_launch(void* const* d_in, const int* in_sizes, int n_in,
                              void* d_out, int out_size) {
    const float* x    = (const float*)d_in[0];
    const float* g1   = (const float*)d_in[1];
    const float* wqkv = (const float*)d_in[2];
    const float* wout = (const float*)d_in[3];
    const float* bout = (const float*)d_in[4];
    const float* g2   = (const float*)d_in[5];
    float* out = (float*)d_out;

    cudaFuncSetAttribute(qkv_kernel, cudaFuncAttributeMaxDynamicSharedMemorySize, K1_SMEM);
    cudaFuncSetAttribute(out_kernel, cudaFuncAttributeMaxDynamicSharedMemorySize, K2_SMEM);

    prep_kernel<<<256, 256>>>(wqkv, g1, wout);
    dim3 grid(NN / 128, BB);
    qkv_kernel<<<grid, 512, K1_SMEM>>>(x);
    out_kernel<<<grid, 512, K2_SMEM>>>(bout, g2, out);
}

// round 8
// speedup vs baseline: 3.0028x; 1.0233x over previous
#include <cuda_runtime.h>
#include <cuda_fp16.h>
#include <cstdint>
#include <math.h>

#define BB 16
#define CC 128
#define NN 16384
#define SQRTC 11.313708498984761f
#define QSCALE 0.17677669529663688f
#define L2E 1.4426950408889634f

// ---- global scratch ----
__device__ __align__(16) __half g_W16[3][128 * 136];   // qkv weights fp16, padded rows
__device__ __align__(16) __half g_Xh[(size_t)2048 * 17408]; // forwarded X-hat operand tiles
__device__ __align__(16) __half g_G[BB][128 * 136];    // fused Wo*ctxA per batch
__device__ float g_ctx[BB * 4 * 32 * 32];
__device__ float g_den[BB * CC];

// =============================== helpers ==================================
__device__ __forceinline__ uint32_t smem_u32(const void* p) {
    uint32_t a;
    asm("{ .reg .u64 t; cvta.to.shared.u64 t, %1; cvt.u32.u64 %0, t; }" : "=r"(a) : "l"(p));
    return a;
}
__device__ __forceinline__ void ldsm4(uint32_t addr, uint32_t& r0, uint32_t& r1,
                                      uint32_t& r2, uint32_t& r3) {
    asm volatile("ldmatrix.sync.aligned.m8n8.x4.shared.b16 {%0,%1,%2,%3}, [%4];"
                 : "=r"(r0), "=r"(r1), "=r"(r2), "=r"(r3) : "r"(addr));
}
__device__ __forceinline__ void mma8(float* c, uint32_t a0, uint32_t a1, uint32_t a2,
                                     uint32_t a3, uint32_t b0, uint32_t b1) {
    asm volatile(
        "mma.sync.aligned.m16n8k16.row.col.f32.f16.f16.f32 "
        "{%0,%1,%2,%3},{%4,%5,%6,%7},{%8,%9},{%0,%1,%2,%3};"
        : "+f"(c[0]), "+f"(c[1]), "+f"(c[2]), "+f"(c[3])
        : "r"(a0), "r"(a1), "r"(a2), "r"(a3), "r"(b0), "r"(b1));
}
// two fp16 exponentials in one MUFU op
__device__ __forceinline__ uint32_t exp2_h2(float v0, float v1) {
    __half2 l = __floats2half2_rn(v0, v1);
    uint32_t e;
    asm("ex2.approx.f16x2 %0, %1;" : "=r"(e) : "r"(*(uint32_t*)&l));
    return e;
}
// GEMM pass: A row-major [m][k], B stored [n][k] (stride 272B both)
template <int KSTEPS, int NT2>
__device__ __forceinline__ void gemm_pass(float* acc, uint32_t aLane, uint32_t bLane) {
    #pragma unroll
    for (int ks = 0; ks < KSTEPS; ks++) {
        uint32_t a0, a1, a2, a3;
        ldsm4(aLane + ks * 32, a0, a1, a2, a3);
        #pragma unroll
        for (int nt = 0; nt < NT2; nt++) {
            uint32_t b0, b1, b2, b3;
            ldsm4(bLane + nt * 4352 + ks * 32, b0, b1, b2, b3);
            mma8(acc + nt * 8,     a0, a1, a2, a3, b0, b1);
            mma8(acc + nt * 8 + 4, a0, a1, a2, a3, b2, b3);
        }
    }
}
__device__ __forceinline__ uint32_t a_lane_addr(uint32_t sb, uint32_t off, int m0,
                                                int rs, int lane) {
    return sb + off + (uint32_t)(m0 + (lane & 15)) * rs + ((lane >> 4) << 4);
}
__device__ __forceinline__ uint32_t b_lane_addr(uint32_t sb, uint32_t off, int lane) {
    return sb + off + (uint32_t)((lane & 7) + ((lane & 16) >> 1)) * 272 + ((lane & 8) << 1);
}

// =============================== diag (ncu alignment) ======================
__global__ void diag_kernel() {}

// =============================== prep ======================================
__global__ void prep_kernel(const float* __restrict__ wqkv, const float* __restrict__ g1) {
    int i = blockIdx.x * 256 + threadIdx.x;   // 65536
    if (i < 49152) {
        int g = i >> 14, r = i & 16383, o = r >> 7, c = r & 127;
        float v = wqkv[((g << 7) + o) * CC + c] * g1[c] * SQRTC;
        g_W16[g][o * 136 + c] = __float2half_rn(v);
    }
    if (i < BB * 4096) g_ctx[i] = 0.f;
    if (i < BB * CC)   g_den[i] = 0.f;
}

// =============================== K1 =======================================
// regions: Wk@0 | Wv@34816 | X@69632 | Xs fp32 @104448 (E/V overlay) | inv @174080
#define K1_WK   0u
#define K1_WV   34816u
#define K1_X    69632u
#define K1_XS   104448u
#define K1_E    104448u
#define K1_V    139264u
#define K1_INV  174080u
#define K1_SMEM 174592

__global__ __launch_bounds__(512, 1) void qkv_kernel(const float* __restrict__ x) {
    extern __shared__ char sm[];
    const uint32_t sb = smem_u32(sm);
    const int tid = threadIdx.x, lane = tid & 31, w = tid >> 5;
    const int b = blockIdx.y, bx = blockIdx.x, p0 = bx << 7;
    float* Xs  = (float*)(sm + K1_XS);
    float* inv = (float*)(sm + K1_INV);

    // phase 0: load x tile + Wk&Wv (contiguous)
    {
        float4* Xs4 = (float4*)Xs;
        const float* xb = x + (((size_t)b) << 21) + p0;
        for (int i = tid; i < 4096; i += 512) {
            int c = i >> 5, t4 = i & 31;
            Xs4[i] = *((const float4*)(xb + ((size_t)c << 14)) + t4);
        }
        const uint4* wsrc = (const uint4*)g_W16[1];
        uint4* wdst = (uint4*)(sm + K1_WK);
        for (int i = tid; i < 4352; i += 512) wdst[i] = wsrc[i];
    }
    __syncthreads();
    // rmsnorm reduce: 2 threads per token
    if (tid < 256) {
        const int t = tid >> 1, half = tid & 1;
        float s = 0.f;
        #pragma unroll 16
        for (int j = 0; j < 64; j++) {
            float v = Xs[(((half << 6) + j) << 7) + t];
            s = fmaf(v, v, s);
        }
        s += __shfl_xor_sync(0xffffffffu, s, 1);
        if (half == 0) inv[t] = 1.0f / fmaxf(sqrtf(s), 1e-12f);
    }
    __syncthreads();
    // pack X operand [t][c] fp16 (inv folded): 4 threads per token
    {
        const int t = tid >> 2, c0 = (tid & 3) << 5;
        const float it = inv[t];
        char* px = sm + K1_X + t * 272;
        #pragma unroll 8
        for (int j = 0; j < 16; j++) {
            int c = c0 + (j << 1);
            __half2 h = __floats2half2_rn(Xs[(c << 7) + t] * it, Xs[((c + 1) << 7) + t] * it);
            *(uint32_t*)(px + c * 2) = *(uint32_t*)&h;
        }
    }
    __syncthreads();
    // export X-hat operand to gmem for K2
    {
        const uint4* s4 = (const uint4*)(sm + K1_X);
        uint4* g4 = (uint4*)g_Xh + (size_t)((b << 7) + bx) * 2176;
        for (int i = tid; i < 2176; i += 512) g4[i] = s4[i];
    }

    const int m0 = (w & 7) << 4, th = w >> 3;
    const int gp = lane >> 2, tq = (lane & 3) << 1;
    const uint32_t bX = b_lane_addr(sb, K1_X + th * 17408u, lane);

    // ---- GEMM k ----
    float acc[32];
    #pragma unroll
    for (int i = 0; i < 32; i++) acc[i] = 0.f;
    gemm_pass<8, 4>(acc, a_lane_addr(sb, K1_WK, m0, 272, lane), bX);

    // epilogue k: exp via ex2.f16x2 -> E, den atomics
    {
        const int r0 = m0 + gp, r1 = r0 + 8;
        float d0 = 0.f, d1 = 0.f;
        #pragma unroll
        for (int nt = 0; nt < 4; nt++) {
            #pragma unroll
            for (int s2 = 0; s2 < 2; s2++) {
                int cb = (th << 6) + (nt << 4) + (s2 << 3) + tq;
                const float* a4 = acc + (nt << 3) + (s2 << 2);
                uint32_t e0 = exp2_h2(a4[0] * L2E, a4[1] * L2E);
                uint32_t e1 = exp2_h2(a4[2] * L2E, a4[3] * L2E);
                *(uint32_t*)(sm + K1_E + r0 * 272 + cb * 2) = e0;
                *(uint32_t*)(sm + K1_E + r1 * 272 + cb * 2) = e1;
                float2 f0 = __half22float2(*(__half2*)&e0);
                float2 f1 = __half22float2(*(__half2*)&e1);
                d0 += f0.x + f0.y;
                d1 += f1.x + f1.y;
            }
        }
        d0 += __shfl_xor_sync(0xffffffffu, d0, 1);
        d0 += __shfl_xor_sync(0xffffffffu, d0, 2);
        d1 += __shfl_xor_sync(0xffffffffu, d1, 1);
        d1 += __shfl_xor_sync(0xffffffffu, d1, 2);
        if ((lane & 3) == 0) {
            atomicAdd(&g_den[(b << 7) + r0], d0);
            atomicAdd(&g_den[(b << 7) + r1], d1);
        }
    }

    // ---- GEMM v ----
    #pragma unroll
    for (int i = 0; i < 32; i++) acc[i] = 0.f;
    gemm_pass<8, 4>(acc, a_lane_addr(sb, K1_WV, m0, 272, lane), bX);
    {
        const int r0 = m0 + gp, r1 = r0 + 8;
        #pragma unroll
        for (int nt = 0; nt < 4; nt++) {
            #pragma unroll
            for (int s2 = 0; s2 < 2; s2++) {
                int cb = (th << 6) + (nt << 4) + (s2 << 3) + tq;
                const float* a4 = acc + (nt << 3) + (s2 << 2);
                __half2 h0 = __floats2half2_rn(a4[0], a4[1]);
                __half2 h1 = __floats2half2_rn(a4[2], a4[3]);
                *(uint32_t*)(sm + K1_V + r0 * 272 + cb * 2) = *(uint32_t*)&h0;
                *(uint32_t*)(sm + K1_V + r1 * 272 + cb * 2) = *(uint32_t*)&h1;
            }
        }
    }
    __syncthreads();

    // ---- gram: ctx[d][e] += sum_t E[d][t] * V[e][t]; warps split token ksteps ----
    {
        const int h = (w & 7) >> 1;
        float acc16[16];
        #pragma unroll
        for (int i = 0; i < 16; i++) acc16[i] = 0.f;
        uint32_t aE = a_lane_addr(sb, K1_E, m0, 272, lane) + th * 128u;
        uint32_t bV = b_lane_addr(sb, K1_V + h * 8704u, lane) + th * 128u;
        gemm_pass<4, 2>(acc16, aE, bV);

        const int dl0 = (m0 + gp) & 31, dl1 = dl0 + 8;
        float* cbase = g_ctx + (((b << 2) + h) << 10);
        #pragma unroll
        for (int nt = 0; nt < 2; nt++) {
            #pragma unroll
            for (int s2 = 0; s2 < 2; s2++) {
                int cb = (nt << 4) + (s2 << 3) + tq;
                const float* a4 = acc16 + (nt << 3) + (s2 << 2);
                atomicAdd(cbase + (dl0 << 5) + cb,     a4[0]);
                atomicAdd(cbase + (dl0 << 5) + cb + 1, a4[1]);
                atomicAdd(cbase + (dl1 << 5) + cb,     a4[2]);
                atomicAdd(cbase + (dl1 << 5) + cb + 1, a4[3]);
            }
        }
    }
}

// =============================== K1.5: G = Wo * ctxA =======================
// grid 16 (one per batch), 256 threads
__global__ __launch_bounds__(256, 1) void g_kernel(const float* __restrict__ wout) {
    __shared__ float ctxn[4096];
    __shared__ float invden[128];
    const int tid = threadIdx.x, b = blockIdx.x;
    if (tid < 128) invden[tid] = 1.0f / g_den[(b << 7) + tid];
    __syncthreads();
    #pragma unroll
    for (int j = 0; j < 16; j++) {
        int idx = tid + (j << 8);
        int h = idx >> 10, d = (idx >> 5) & 31;
        ctxn[idx] = g_ctx[(b << 12) + idx] * invden[(h << 5) + d];
    }
    __syncthreads();
    // thread: o = tid&127, heads {2*(tid>>7), 2*(tid>>7)+1}
    const int o = tid & 127, h0 = (tid >> 7) << 1;
    #pragma unroll
    for (int hh = 0; hh < 2; hh++) {
        int h = h0 + hh;
        float4 wr[8];
        const float4* wsrc = (const float4*)(wout + (o << 7) + (h << 5));
        #pragma unroll
        for (int j = 0; j < 8; j++) wr[j] = wsrc[j];
        #pragma unroll
        for (int d = 0; d < 32; d++) {
            const float4* cr = (const float4*)(ctxn + (h << 10) + (d << 5));
            float a = 0.f;
            #pragma unroll
            for (int j = 0; j < 8; j++) {
                float4 c4 = cr[j];
                a = fmaf(wr[j].x, c4.x, a);
                a = fmaf(wr[j].y, c4.y, a);
                a = fmaf(wr[j].z, c4.z, a);
                a = fmaf(wr[j].w, c4.w, a);
            }
            g_G[b][o * 136 + (h << 5) + d] = __float2half_rn(a);
        }
    }
}

// =============================== K2 =======================================
// regions: Wq@0 (Bp overlay) | X@34816 | QL@69632 fp32 s132 (Ys overlay)
//          G@137216 | bias@172032 | g2@172544 | invs@173056
#define K2_WQ   0u
#define K2_BP   0u
#define K2_X    34816u
#define K2_QL   69632u
#define K2_YS   69632u
#define K2_G    137216u
#define K2_BIAS 172032u
#define K2_G2   172544u
#define K2_INVS 173056u
#define K2_SMEM 173568

__global__ __launch_bounds__(512, 1) void out_kernel(const float* __restrict__ b_out,
                                                     const float* __restrict__ g2,
                                                     float* __restrict__ out) {
    extern __shared__ char sm[];
    const uint32_t sb = smem_u32(sm);
    const int tid = threadIdx.x, lane = tid & 31, w = tid >> 5;
    const int b = blockIdx.y, bx = blockIdx.x, p0 = bx << 7;
    float* QL   = (float*)(sm + K2_QL);      // stride 132
    float* Ys   = (float*)(sm + K2_YS);      // stride 132
    float* invs = (float*)(sm + K2_INVS);
    float* bs   = (float*)(sm + K2_BIAS);
    float* g2s  = (float*)(sm + K2_G2);

    // phase 0: all loads (X-hat, Wq, G, bias, g2)
    {
        const uint4* xsrc = (const uint4*)g_Xh + (size_t)((b << 7) + bx) * 2176;
        uint4* xdst = (uint4*)(sm + K2_X);
        for (int i = tid; i < 2176; i += 512) xdst[i] = xsrc[i];
        const uint4* wsrc = (const uint4*)g_W16[0];
        uint4* wdst = (uint4*)(sm + K2_WQ);
        for (int i = tid; i < 2176; i += 512) wdst[i] = wsrc[i];
        const uint4* gsrc = (const uint4*)g_G[b];
        uint4* gdst = (uint4*)(sm + K2_G);
        for (int i = tid; i < 2176; i += 512) gdst[i] = gsrc[i];
        if (tid < 128) { bs[tid] = b_out[tid]; g2s[tid] = g2[tid]; }
    }
    __syncthreads();

    const int m0 = (w & 7) << 4, th = w >> 3;
    const int gp = lane >> 2, tq = (lane & 3) << 1;

    // ---- GEMM q ----
    float acc[32];
    #pragma unroll
    for (int i = 0; i < 32; i++) acc[i] = 0.f;
    gemm_pass<8, 4>(acc, a_lane_addr(sb, K2_WQ, m0, 272, lane),
                    b_lane_addr(sb, K2_X + th * 17408u, lane));
    {
        const int r0 = m0 + gp, r1 = r0 + 8;
        #pragma unroll
        for (int nt = 0; nt < 4; nt++) {
            #pragma unroll
            for (int s2 = 0; s2 < 2; s2++) {
                int cb = (th << 6) + (nt << 4) + (s2 << 3) + tq;
                const float* a4 = acc + (nt << 3) + (s2 << 2);
                *(float2*)(QL + r0 * 132 + cb) = make_float2(a4[0], a4[1]);
                *(float2*)(QL + r1 * 132 + cb) = make_float2(a4[2], a4[3]);
            }
        }
    }
    __syncthreads();

    // ---- softmax via ex2.f16x2: one (token, head) per thread -> Bp ----
    {
        const int t = tid & 127, h = tid >> 7;
        char* pb = sm + K2_BP + t * 272 + (h << 6);
        float pv[32];
        float m = -1e30f;
        #pragma unroll 8
        for (int d = 0; d < 32; d++) {
            pv[d] = QL[((h << 5) + d) * 132 + t];
            m = fmaxf(m, pv[d]);
        }
        uint32_t eh[16];
        float s = 0.f;
        #pragma unroll
        for (int d2 = 0; d2 < 16; d2++) {
            eh[d2] = exp2_h2((pv[d2 << 1] - m) * L2E, (pv[(d2 << 1) + 1] - m) * L2E);
            float2 f = __half22float2(*(__half2*)&eh[d2]);
            s += f.x + f.y;
        }
        __half2 r2 = __float2half2_rn(QSCALE / s);
        #pragma unroll
        for (int d2 = 0; d2 < 16; d2++) {
            __half2 p2 = __hmul2(*(__half2*)&eh[d2], r2);
            *(uint32_t*)(pb + (d2 << 2)) = *(uint32_t*)&p2;
        }
    }
    __syncthreads();

    // ---- GEMM y: y[o][t] = sum_d G[o][d] * p[t][d] ----
    #pragma unroll
    for (int i = 0; i < 32; i++) acc[i] = 0.f;
    gemm_pass<8, 4>(acc, a_lane_addr(sb, K2_G, m0, 272, lane),
                    b_lane_addr(sb, K2_BP + th * 17408u, lane));
    // Ys epilogue over QL region (dead after softmax; Bp reads untouched)
    {
        const int r0 = m0 + gp, r1 = r0 + 8;
        const float b0v = bs[r0], b1v = bs[r1];
        #pragma unroll
        for (int nt = 0; nt < 4; nt++) {
            #pragma unroll
            for (int s2 = 0; s2 < 2; s2++) {
                int cb = (th << 6) + (nt << 4) + (s2 << 3) + tq;
                const float* a4 = acc + (nt << 3) + (s2 << 2);
                *(float2*)(Ys + r0 * 132 + cb) = make_float2(a4[0] + b0v, a4[1] + b0v);
                *(float2*)(Ys + r1 * 132 + cb) = make_float2(a4[2] + b1v, a4[3] + b1v);
            }
        }
    }
    __syncthreads();
    // rmsnorm reduce: 4 threads per token
    {
        const int t = tid >> 2, q4 = tid & 3;
        float s = 0.f;
        #pragma unroll 8
        for (int j = 0; j < 32; j++) {
            float v = Ys[((q4 << 5) + j) * 132 + t];
            s = fmaf(v, v, s);
        }
        s += __shfl_xor_sync(0xffffffffu, s, 1);
        s += __shfl_xor_sync(0xffffffffu, s, 2);
        if (q4 == 0) invs[t] = SQRTC / fmaxf(sqrtf(s), 1e-12f);
    }
    __syncthreads();
    {
        const int to = tid & 127, oh = (tid >> 7) << 5;
        const float iv = invs[to];
        float* ob = out + (((size_t)b) << 21) + p0 + to;
        #pragma unroll 8
        for (int j = 0; j < 32; j++) {
            int o = oh + j;
            ob[(size_t)o << 14] = Ys[o * 132 + to] * iv * g2s[o];
        }
    }
}

// ---------------------------------------------------------------------------
extern "C" void kernel_launch(void* const* d_in, const int* in_sizes, int n_in,
                              void* d_out, int out_size) {
    const float* x    = (const float*)d_in[0];
    const float* g1   = (const float*)d_in[1];
    const float* wqkv = (const float*)d_in[2];
    const float* wout = (const float*)d_in[3];
    const float* bout = (const float*)d_in[4];
    const float* g2   = (const float*)d_in[5];
    float* out = (float*)d_out;

    cudaFuncSetAttribute(qkv_kernel, cudaFuncAttributeMaxDynamicSharedMemorySize, K1_SMEM);
    cudaFuncSetAttribute(out_kernel, cudaFuncAttributeMaxDynamicSharedMemorySize, K2_SMEM);

    diag_kernel<<<1, 32>>>();
    prep_kernel<<<256, 256>>>(wqkv, g1);
    dim3 grid(NN / 128, BB);
    qkv_kernel<<<grid, 512, K1_SMEM>>>(x);
    g_kernel<<<BB, 256>>>(wout);
    out_kernel<<<grid, 512, K2_SMEM>>>(bout, g2, out);
}

// round 9
// speedup vs baseline: 4.5932x; 1.5297x over previous
#include <cuda_runtime.h>
#include <cuda_fp16.h>
#include <cstdint>
#include <math.h>

#define BB 16
#define CC 128
#define NN 16384
#define GRID 148
#define NTILES 2048
#define SQRTC 11.313708498984761f
#define QSCALE 0.17677669529663688f
#define L2E 1.4426950408889634f

// ---- global scratch ----
__device__ __align__(16) __half g_W16[3][128 * 136];   // qkv weights fp16, padded rows
__device__ __align__(16) __half g_Xh[(size_t)2048 * 17408]; // forwarded X-hat operand tiles
__device__ __align__(16) __half g_G[BB][128 * 136];    // fused Wo*ctxA per batch
__device__ float g_ctx[BB * 4 * 32 * 32];
__device__ float g_den[BB * CC];

// =============================== helpers ==================================
__device__ __forceinline__ uint32_t smem_u32(const void* p) {
    uint32_t a;
    asm("{ .reg .u64 t; cvta.to.shared.u64 t, %1; cvt.u32.u64 %0, t; }" : "=r"(a) : "l"(p));
    return a;
}
__device__ __forceinline__ void ldsm4(uint32_t addr, uint32_t& r0, uint32_t& r1,
                                      uint32_t& r2, uint32_t& r3) {
    asm volatile("ldmatrix.sync.aligned.m8n8.x4.shared.b16 {%0,%1,%2,%3}, [%4];"
                 : "=r"(r0), "=r"(r1), "=r"(r2), "=r"(r3) : "r"(addr));
}
__device__ __forceinline__ void mma8(float* c, uint32_t a0, uint32_t a1, uint32_t a2,
                                     uint32_t a3, uint32_t b0, uint32_t b1) {
    asm volatile(
        "mma.sync.aligned.m16n8k16.row.col.f32.f16.f16.f32 "
        "{%0,%1,%2,%3},{%4,%5,%6,%7},{%8,%9},{%0,%1,%2,%3};"
        : "+f"(c[0]), "+f"(c[1]), "+f"(c[2]), "+f"(c[3])
        : "r"(a0), "r"(a1), "r"(a2), "r"(a3), "r"(b0), "r"(b1));
}
__device__ __forceinline__ uint32_t exp2_h2(float v0, float v1) {
    __half2 l = __floats2half2_rn(v0, v1);
    uint32_t e;
    asm("ex2.approx.f16x2 %0, %1;" : "=r"(e) : "r"(*(uint32_t*)&l));
    return e;
}
#define CP_ASYNC16(saddr, gptr) \
    asm volatile("cp.async.cg.shared.global [%0], [%1], 16;" :: "r"((uint32_t)(saddr)), "l"(gptr))
#define CP_COMMIT() asm volatile("cp.async.commit_group;" ::: "memory")
#define CP_WAIT0()  asm volatile("cp.async.wait_group 0;" ::: "memory")

// GEMM pass: A row-major [m][k], B stored [n][k] (stride 272B both)
template <int KSTEPS, int NT2>
__device__ __forceinline__ void gemm_pass(float* acc, uint32_t aLane, uint32_t bLane) {
    #pragma unroll
    for (int ks = 0; ks < KSTEPS; ks++) {
        uint32_t a0, a1, a2, a3;
        ldsm4(aLane + ks * 32, a0, a1, a2, a3);
        #pragma unroll
        for (int nt = 0; nt < NT2; nt++) {
            uint32_t b0, b1, b2, b3;
            ldsm4(bLane + nt * 4352 + ks * 32, b0, b1, b2, b3);
            mma8(acc + nt * 8,     a0, a1, a2, a3, b0, b1);
            mma8(acc + nt * 8 + 4, a0, a1, a2, a3, b2, b3);
        }
    }
}
__device__ __forceinline__ uint32_t a_lane_addr(uint32_t sb, uint32_t off, int m0,
                                                int rs, int lane) {
    return sb + off + (uint32_t)(m0 + (lane & 15)) * rs + ((lane >> 4) << 4);
}
__device__ __forceinline__ uint32_t b_lane_addr(uint32_t sb, uint32_t off, int lane) {
    return sb + off + (uint32_t)((lane & 7) + ((lane & 16) >> 1)) * 272 + ((lane & 8) << 1);
}

// =============================== diag (ncu alignment) ======================
__global__ void diag_kernel() {}

// =============================== prep ======================================
__global__ void prep_kernel(const float* __restrict__ wqkv, const float* __restrict__ g1) {
    int i = blockIdx.x * 256 + threadIdx.x;   // 65536
    if (i < 49152) {
        int g = i >> 14, r = i & 16383, o = r >> 7, c = r & 127;
        float v = wqkv[((g << 7) + o) * CC + c] * g1[c] * SQRTC;
        g_W16[g][o * 136 + c] = __float2half_rn(v);
    }
    if (i < BB * 4096) g_ctx[i] = 0.f;
    if (i < BB * CC)   g_den[i] = 0.f;
}

// =============================== K1 (persistent) ===========================
// regions: Wk@0 | Wv@34816 | X@69632 | E@104448 | V@139264
#define K1_WK   0u
#define K1_WV   34816u
#define K1_X    69632u
#define K1_E    104448u
#define K1_V    139264u
#define K1_SMEM 174080

__global__ __launch_bounds__(512, 1) void qkv_kernel(const float* __restrict__ x) {
    extern __shared__ char sm[];
    const uint32_t sb = smem_u32(sm);
    const int tid = threadIdx.x, lane = tid & 31, w = tid >> 5;

    // weights once (Wk, Wv contiguous = g_W16[1], g_W16[2])
    {
        const uint4* wsrc = (const uint4*)g_W16[1];
        uint4* wdst = (uint4*)(sm + K1_WK);
        for (int i = tid; i < 4352; i += 512) wdst[i] = wsrc[i];
    }
    const int t = tid >> 2, cq = tid & 3;
    const int m0 = (w & 7) << 4, th = w >> 3;
    const int gp = lane >> 2, tq = (lane & 3) << 1;
    const uint32_t bX = b_lane_addr(sb, K1_X + th * 17408u, lane);
    const uint32_t aWk = a_lane_addr(sb, K1_WK, m0, 272, lane);
    const uint32_t aWv = a_lane_addr(sb, K1_WV, m0, 272, lane);

    int idx = blockIdx.x;
    float xr[32];
    {
        const float* xb = x + ((size_t)(idx >> 7) << 21) + ((idx & 127) << 7) + t;
        #pragma unroll
        for (int j = 0; j < 32; j++) xr[j] = xb[(size_t)(cq * 32 + j) << 14];
    }

    while (true) {
        const int b = idx >> 7;
        // rmsnorm (register/shfl only)
        float s = 0.f;
        #pragma unroll
        for (int j = 0; j < 32; j++) s = fmaf(xr[j], xr[j], s);
        s += __shfl_xor_sync(0xffffffffu, s, 1);
        s += __shfl_xor_sync(0xffffffffu, s, 2);
        const float it = 1.0f / fmaxf(sqrtf(s), 1e-12f);
        // pack own 32 channels into X operand row t
        {
            char* px = sm + K1_X + t * 272 + (cq << 6);
            #pragma unroll
            for (int j2 = 0; j2 < 16; j2++) {
                __half2 h = __floats2half2_rn(xr[2 * j2] * it, xr[2 * j2 + 1] * it);
                *(uint32_t*)(px + (j2 << 2)) = *(uint32_t*)&h;
            }
        }
        __syncthreads();   // B1: X visible; prior-iter E/V reads (gram) drained
        // export X-hat
        {
            const uint4* s4 = (const uint4*)(sm + K1_X);
            uint4* g4 = (uint4*)g_Xh + (size_t)idx * 2176;
            for (int i = tid; i < 2176; i += 512) g4[i] = s4[i];
        }
        // ---- GEMM k ----
        float acc[32];
        #pragma unroll
        for (int i = 0; i < 32; i++) acc[i] = 0.f;
        gemm_pass<8, 4>(acc, aWk, bX);
        // epilogue k: exp -> E, den atomics
        {
            const int r0 = m0 + gp, r1 = r0 + 8;
            float d0 = 0.f, d1 = 0.f;
            #pragma unroll
            for (int nt = 0; nt < 4; nt++) {
                #pragma unroll
                for (int s2 = 0; s2 < 2; s2++) {
                    int cb = (th << 6) + (nt << 4) + (s2 << 3) + tq;
                    const float* a4 = acc + (nt << 3) + (s2 << 2);
                    uint32_t e0 = exp2_h2(a4[0] * L2E, a4[1] * L2E);
                    uint32_t e1 = exp2_h2(a4[2] * L2E, a4[3] * L2E);
                    *(uint32_t*)(sm + K1_E + r0 * 272 + cb * 2) = e0;
                    *(uint32_t*)(sm + K1_E + r1 * 272 + cb * 2) = e1;
                    float2 f0 = __half22float2(*(__half2*)&e0);
                    float2 f1 = __half22float2(*(__half2*)&e1);
                    d0 += f0.x + f0.y;
                    d1 += f1.x + f1.y;
                }
            }
            d0 += __shfl_xor_sync(0xffffffffu, d0, 1);
            d0 += __shfl_xor_sync(0xffffffffu, d0, 2);
            d1 += __shfl_xor_sync(0xffffffffu, d1, 1);
            d1 += __shfl_xor_sync(0xffffffffu, d1, 2);
            if ((lane & 3) == 0) {
                atomicAdd(&g_den[(b << 7) + r0], d0);
                atomicAdd(&g_den[(b << 7) + r1], d1);
            }
        }
        // prefetch next x tile into registers (hidden under v GEMM + gram)
        const int nidx = idx + GRID;
        const bool more = nidx < NTILES;
        if (more) {
            const float* xb = x + ((size_t)(nidx >> 7) << 21) + ((nidx & 127) << 7) + t;
            #pragma unroll
            for (int j = 0; j < 32; j++) xr[j] = xb[(size_t)(cq * 32 + j) << 14];
        }
        // ---- GEMM v ----
        #pragma unroll
        for (int i = 0; i < 32; i++) acc[i] = 0.f;
        gemm_pass<8, 4>(acc, aWv, bX);
        {
            const int r0 = m0 + gp, r1 = r0 + 8;
            #pragma unroll
            for (int nt = 0; nt < 4; nt++) {
                #pragma unroll
                for (int s2 = 0; s2 < 2; s2++) {
                    int cb = (th << 6) + (nt << 4) + (s2 << 3) + tq;
                    const float* a4 = acc + (nt << 3) + (s2 << 2);
                    __half2 h0 = __floats2half2_rn(a4[0], a4[1]);
                    __half2 h1 = __floats2half2_rn(a4[2], a4[3]);
                    *(uint32_t*)(sm + K1_V + r0 * 272 + cb * 2) = *(uint32_t*)&h0;
                    *(uint32_t*)(sm + K1_V + r1 * 272 + cb * 2) = *(uint32_t*)&h1;
                }
            }
        }
        __syncthreads();   // B2: E, V visible
        // ---- gram: ctx[d][e] += sum_t E[d][t]*V[e][t] (per-head diag blocks) ----
        {
            const int h = (w & 7) >> 1;
            float acc16[16];
            #pragma unroll
            for (int i = 0; i < 16; i++) acc16[i] = 0.f;
            uint32_t aE = a_lane_addr(sb, K1_E, m0, 272, lane) + th * 128u;
            uint32_t bV = b_lane_addr(sb, K1_V + h * 8704u, lane) + th * 128u;
            gemm_pass<4, 2>(acc16, aE, bV);

            const int dl0 = (m0 + gp) & 31, dl1 = dl0 + 8;
            float* cbase = g_ctx + (((b << 2) + h) << 10);
            #pragma unroll
            for (int nt = 0; nt < 2; nt++) {
                #pragma unroll
                for (int s2 = 0; s2 < 2; s2++) {
                    int cb = (nt << 4) + (s2 << 3) + tq;
                    const float* a4 = acc16 + (nt << 3) + (s2 << 2);
                    atomicAdd(cbase + (dl0 << 5) + cb,     a4[0]);
                    atomicAdd(cbase + (dl0 << 5) + cb + 1, a4[1]);
                    atomicAdd(cbase + (dl1 << 5) + cb,     a4[2]);
                    atomicAdd(cbase + (dl1 << 5) + cb + 1, a4[3]);
                }
            }
        }
        if (!more) return;
        idx = nidx;
    }
}

// =============================== K1.5: G = Wo * ctxA =======================
// grid 64 = (b,h), 256 threads
__global__ __launch_bounds__(256, 1) void g_kernel(const float* __restrict__ wout) {
    __shared__ float ctxn[1024];
    __shared__ float invden[32];
    const int tid = threadIdx.x;
    const int b = blockIdx.x >> 2, h = blockIdx.x & 3;
    if (tid < 32) invden[tid] = 1.0f / g_den[(b << 7) + (h << 5) + tid];
    __syncthreads();
    #pragma unroll
    for (int j0 = 0; j0 < 4; j0++) {
        int j = tid + (j0 << 8);
        ctxn[j] = g_ctx[(b << 12) + (h << 10) + j] * invden[j >> 5];
    }
    __syncthreads();
    const int o = tid & 127, dh = (tid >> 7) << 4;
    float4 wr[8];
    const float4* wsrc = (const float4*)(wout + (o << 7) + (h << 5));
    #pragma unroll
    for (int j = 0; j < 8; j++) wr[j] = wsrc[j];
    #pragma unroll
    for (int dd = 0; dd < 16; dd++) {
        int d = dh + dd;
        const float4* cr = (const float4*)(ctxn + (d << 5));
        float a = 0.f;
        #pragma unroll
        for (int j = 0; j < 8; j++) {
            float4 c4 = cr[j];
            a = fmaf(wr[j].x, c4.x, a);
            a = fmaf(wr[j].y, c4.y, a);
            a = fmaf(wr[j].z, c4.z, a);
            a = fmaf(wr[j].w, c4.w, a);
        }
        g_G[b][o * 136 + (h << 5) + d] = __float2half_rn(a);
    }
}

// =============================== K2 (persistent) ===========================
// regions: Wq@0 | X0@34816 | X1@69632 | G@104448 | QL fp16 s272 @139264 (Ys fp32 s132 overlay)
//          Bp@174080 | bias@208896 | g2@209408 | invs@209920
#define K2_WQ   0u
#define K2_X0   34816u
#define K2_X1   69632u
#define K2_G    104448u
#define K2_QL   139264u
#define K2_YS   139264u
#define K2_BP   174080u
#define K2_BIAS 208896u
#define K2_G2   209408u
#define K2_INVS 209920u
#define K2_SMEM 210432

__global__ __launch_bounds__(512, 1) void out_kernel(const float* __restrict__ b_out,
                                                     const float* __restrict__ g2,
                                                     float* __restrict__ out) {
    extern __shared__ char sm[];
    const uint32_t sb = smem_u32(sm);
    const int tid = threadIdx.x, lane = tid & 31, w = tid >> 5;
    float* Ys   = (float*)(sm + K2_YS);      // fp32 stride 132
    float* invs = (float*)(sm + K2_INVS);
    float* bs   = (float*)(sm + K2_BIAS);
    float* g2s  = (float*)(sm + K2_G2);

    // once: Wq, bias, g2
    {
        const uint4* wsrc = (const uint4*)g_W16[0];
        uint4* wdst = (uint4*)(sm + K2_WQ);
        for (int i = tid; i < 2176; i += 512) wdst[i] = wsrc[i];
        if (tid < 128) { bs[tid] = b_out[tid]; g2s[tid] = g2[tid]; }
    }
    const int m0 = (w & 7) << 4, th = w >> 3;
    const int gp = lane >> 2, tq = (lane & 3) << 1;
    const uint32_t aWq = a_lane_addr(sb, K2_WQ, m0, 272, lane);
    const uint32_t aG  = a_lane_addr(sb, K2_G,  m0, 272, lane);

    int idx = blockIdx.x;
    uint32_t xoff = K2_X0;
    // preload first X-hat tile
    {
        const uint4* src = (const uint4*)g_Xh + (size_t)idx * 2176;
        for (int i = tid; i < 2176; i += 512)
            CP_ASYNC16(sb + K2_X0 + (uint32_t)i * 16, src + i);
        CP_COMMIT();
    }

    while (true) {
        const int b = idx >> 7, p0 = (idx & 127) << 7;
        // G load (L2-hot)
        {
            const uint4* gsrc = (const uint4*)g_G[b];
            uint4* gdst = (uint4*)(sm + K2_G);
            for (int i = tid; i < 2176; i += 512) gdst[i] = gsrc[i];
        }
        CP_WAIT0();
        __syncthreads();   // B1: Xcur + G visible; prior Ys readers drained
        // ---- GEMM q ----
        float acc[32];
        #pragma unroll
        for (int i = 0; i < 32; i++) acc[i] = 0.f;
        gemm_pass<8, 4>(acc, aWq, b_lane_addr(sb, xoff + th * 17408u, lane));
        // QL fp16 store
        {
            const int r0 = m0 + gp, r1 = r0 + 8;
            #pragma unroll
            for (int nt = 0; nt < 4; nt++) {
                #pragma unroll
                for (int s2 = 0; s2 < 2; s2++) {
                    int cb = (th << 6) + (nt << 4) + (s2 << 3) + tq;
                    const float* a4 = acc + (nt << 3) + (s2 << 2);
                    __half2 h0 = __floats2half2_rn(a4[0], a4[1]);
                    __half2 h1 = __floats2half2_rn(a4[2], a4[3]);
                    *(uint32_t*)(sm + K2_QL + r0 * 272 + cb * 2) = *(uint32_t*)&h0;
                    *(uint32_t*)(sm + K2_QL + r1 * 272 + cb * 2) = *(uint32_t*)&h1;
                }
            }
        }
        // prefetch next X-hat tile into alternate buffer
        const int nidx = idx + GRID;
        const bool more = nidx < NTILES;
        if (more) {
            const uint32_t dst = sb + (xoff ^ (K2_X0 ^ K2_X1));
            const uint4* src = (const uint4*)g_Xh + (size_t)nidx * 2176;
            for (int i = tid; i < 2176; i += 512)
                CP_ASYNC16(dst + (uint32_t)i * 16, src + i);
            CP_COMMIT();
        }
        __syncthreads();   // B2: QL visible
        // ---- softmax: one (token, head) per thread -> Bp ----
        {
            const int t = tid & 127, h = tid >> 7;
            char* pb = sm + K2_BP + t * 272 + (h << 6);
            float pv[32];
            float m = -1e30f;
            #pragma unroll 8
            for (int d = 0; d < 32; d++) {
                pv[d] = __half2float(*(__half*)(sm + K2_QL + ((h << 5) + d) * 272 + t * 2));
                m = fmaxf(m, pv[d]);
            }
            uint32_t eh[16];
            float s = 0.f;
            #pragma unroll
            for (int d2 = 0; d2 < 16; d2++) {
                eh[d2] = exp2_h2((pv[d2 << 1] - m) * L2E, (pv[(d2 << 1) + 1] - m) * L2E);
                float2 f = __half22float2(*(__half2*)&eh[d2]);
                s += f.x + f.y;
            }
            __half2 r2 = __float2half2_rn(QSCALE / s);
            #pragma unroll
            for (int d2 = 0; d2 < 16; d2++) {
                __half2 p2 = __hmul2(*(__half2*)&eh[d2], r2);
                *(uint32_t*)(pb + (d2 << 2)) = *(uint32_t*)&p2;
            }
        }
        __syncthreads();   // B3: Bp visible
        // ---- GEMM y: y[o][t] = sum_d G[o][d] * p[t][d] ----
        #pragma unroll
        for (int i = 0; i < 32; i++) acc[i] = 0.f;
        gemm_pass<8, 4>(acc, aG, b_lane_addr(sb, K2_BP + th * 17408u, lane));
        __syncthreads();   // B4: QL/Bp reads done -> Ys overwrite safe
        {
            const int r0 = m0 + gp, r1 = r0 + 8;
            const float b0v = bs[r0], b1v = bs[r1];
            #pragma unroll
            for (int nt = 0; nt < 4; nt++) {
                #pragma unroll
                for (int s2 = 0; s2 < 2; s2++) {
                    int cb = (th << 6) + (nt << 4) + (s2 << 3) + tq;
                    const float* a4 = acc + (nt << 3) + (s2 << 2);
                    *(float2*)(Ys + r0 * 132 + cb) = make_float2(a4[0] + b0v, a4[1] + b0v);
                    *(float2*)(Ys + r1 * 132 + cb) = make_float2(a4[2] + b1v, a4[3] + b1v);
                }
            }
        }
        __syncthreads();   // B5: Ys visible
        // rmsnorm reduce: 4 threads per token
        {
            const int t = tid >> 2, q4 = tid & 3;
            float s = 0.f;
            #pragma unroll 8
            for (int j = 0; j < 32; j++) {
                float v = Ys[((q4 << 5) + j) * 132 + t];
                s = fmaf(v, v, s);
            }
            s += __shfl_xor_sync(0xffffffffu, s, 1);
            s += __shfl_xor_sync(0xffffffffu, s, 2);
            if (q4 == 0) invs[t] = SQRTC / fmaxf(sqrtf(s), 1e-12f);
        }
        __syncthreads();   // B6: invs visible
        {
            const int to = tid & 127, oh = (tid >> 7) << 5;
            const float iv = invs[to];
            float* ob = out + (((size_t)b) << 21) + p0 + to;
            #pragma unroll 8
            for (int j = 0; j < 32; j++) {
                int o = oh + j;
                ob[(size_t)o << 14] = Ys[o * 132 + to] * iv * g2s[o];
            }
        }
        if (!more) return;
        idx = nidx;
        xoff ^= (K2_X0 ^ K2_X1);
    }
}

// ---------------------------------------------------------------------------
extern "C" void kernel_launch(void* const* d_in, const int* in_sizes, int n_in,
                              void* d_out, int out_size) {
    const float* x    = (const float*)d_in[0];
    const float* g1   = (const float*)d_in[1];
    const float* wqkv = (const float*)d_in[2];
    const float* wout = (const float*)d_in[3];
    const float* bout = (const float*)d_in[4];
    const float* g2   = (const float*)d_in[5];
    float* out = (float*)d_out;

    cudaFuncSetAttribute(qkv_kernel, cudaFuncAttributeMaxDynamicSharedMemorySize, K1_SMEM);
    cudaFuncSetAttribute(out_kernel, cudaFuncAttributeMaxDynamicSharedMemorySize, K2_SMEM);

    diag_kernel<<<1, 32>>>();
    diag_kernel<<<1, 32>>>();
    prep_kernel<<<256, 256>>>(wqkv, g1);
    qkv_kernel<<<GRID, 512, K1_SMEM>>>(x);
    g_kernel<<<64, 256>>>(wout);
    out_kernel<<<GRID, 512, K2_SMEM>>>(bout, g2, out);
}